// round 9
// baseline (speedup 1.0000x reference)
#include <cuda_runtime.h>
#include <cuda_bf16.h>
#include <math.h>
#include <stdint.h>

typedef unsigned long long ull;

// ---------------- problem constants ----------------
#define NB    256
#define INF   135
#define INN   120
#define OUTN  24
#define KQ    10
#define VL    34
#define VN    87
#define DCTN  34

#define N1K   23296
#define N2K   22272
#define N1Q   1280
#define N2Q   256

#define LDPF  30720
#define LDQ1  3072
#define NPOS1 30720
#define NPOS2 24576

#define BN_SCALEF 0.9999950000374997f

// ---------------- scratch ----------------
__device__ __align__(128) float g_postf[INF*LDPF];
__device__ __align__(128) __nv_bfloat16 g_pfTh[NPOS1*160];
__device__ __align__(128) __nv_bfloat16 g_pfTl[NPOS1*160];
__device__ __align__(128) __nv_bfloat16 g_w1h[512*960];
__device__ __align__(128) __nv_bfloat16 g_w1l[512*960];
__device__ __align__(128) __nv_bfloat16 g_w2h[512*2560];
__device__ __align__(128) __nv_bfloat16 g_w2l[512*2560];
__device__ __align__(128) __nv_bfloat16 g_h1kTh[NPOS2*512];
__device__ __align__(128) __nv_bfloat16 g_h1kTl[NPOS2*512];
__device__ __align__(128) float g_q1p[512*816];
__device__ __align__(128) float g_q2p[512*2560];
__device__ __align__(128) float g_h1q[512*LDQ1];
__device__ __align__(128) float g_keyf[512*N2K];
__device__ __align__(128) float g_qryf[512*N2Q];
__device__ __align__(128) float g_part[3*512*1280];
__device__ __align__(128) float g_att[NB*VN];
__device__ __align__(128) float g_attT[6*135*144];
__device__ __align__(128) __nv_bfloat16 g_atth[5*144*160];
__device__ __align__(128) __nv_bfloat16 g_attl[5*144*160];
__device__ __align__(128) float g_x[NB*INF*68];
__device__ __align__(128) float g_t1[34560*512];
__device__ __align__(128) __nv_bfloat16 g_t1h[(34560+192)*512];
__device__ __align__(128) __nv_bfloat16 g_t1l[(34560+192)*512];
__device__ __align__(128) float g_t2[34560*512];
__device__ __align__(128) float g_y[34560*512];
__device__ __align__(128) float g_dct[VL*VL];
__device__ __align__(128) __nv_bfloat16 g_s0h[(34560+192)*512];
__device__ __align__(128) __nv_bfloat16 g_s0l[(34560+192)*512];
__device__ __align__(128) __nv_bfloat16 g_s1h[(34560+192)*512];
__device__ __align__(128) __nv_bfloat16 g_s1l[(34560+192)*512];
__device__ __align__(128) __nv_bfloat16 g_wth[4*512*512];
__device__ __align__(128) __nv_bfloat16 g_wtl[4*512*512];

// ---------------- f32x2 helpers ----------------
__device__ __forceinline__ ull packf2(float v) {
    ull r; asm("mov.b64 %0, {%1, %2};" : "=l"(r) : "f"(v), "f"(v)); return r;
}
__device__ __forceinline__ void ffma2(ull &d, ull a, ull b) {
    asm("fma.rn.f32x2 %0, %1, %2, %0;" : "+l"(d) : "l"(a), "l"(b));
}
__device__ __forceinline__ float2 unpk(ull v) {
    float2 r; asm("mov.b64 {%0, %1}, %2;" : "=f"(r.x), "=f"(r.y) : "l"(v)); return r;
}

// ---------------- MMA / async helpers ----------------
__device__ __forceinline__ uint32_t smem_u32(const void* p) {
    uint32_t a;
    asm("{ .reg .u64 t; cvta.to.shared.u64 t, %1; cvt.u32.u64 %0, t; }" : "=r"(a) : "l"(p));
    return a;
}
__device__ __forceinline__ void ldsm4(uint32_t* r, uint32_t addr) {
    asm volatile("ldmatrix.sync.aligned.m8n8.x4.shared.b16 {%0,%1,%2,%3}, [%4];"
        : "=r"(r[0]), "=r"(r[1]), "=r"(r[2]), "=r"(r[3]) : "r"(addr));
}
__device__ __forceinline__ void ldsm4t(uint32_t* r, uint32_t addr) {
    asm volatile("ldmatrix.sync.aligned.m8n8.x4.trans.shared.b16 {%0,%1,%2,%3}, [%4];"
        : "=r"(r[0]), "=r"(r[1]), "=r"(r[2]), "=r"(r[3]) : "r"(addr));
}
__device__ __forceinline__ void mma16816(float* c, const uint32_t* a,
                                         uint32_t b0, uint32_t b1) {
    asm volatile("mma.sync.aligned.m16n8k16.row.col.f32.bf16.bf16.f32 "
        "{%0,%1,%2,%3}, {%4,%5,%6,%7}, {%8,%9}, {%0,%1,%2,%3};"
        : "+f"(c[0]), "+f"(c[1]), "+f"(c[2]), "+f"(c[3])
        : "r"(a[0]), "r"(a[1]), "r"(a[2]), "r"(a[3]), "r"(b0), "r"(b1));
}
__device__ __forceinline__ void cpa(uint32_t s, const void* g) {
    asm volatile("cp.async.cg.shared.global [%0], [%1], 16;" :: "r"(s), "l"(g));
}
#define CP_COMMIT() asm volatile("cp.async.commit_group;" ::: "memory")
#define CP_WAIT(n)  asm volatile("cp.async.wait_group %0;" :: "n"(n) : "memory")

// ---------------- small setup kernels ----------------
__global__ void init_dct() {
    int i = blockIdx.x * 256 + threadIdx.x;
    if (i >= VL*VL) return;
    int k = i / VL, t = i % VL;
    double w = (k == 0) ? sqrt(1.0/VL) : sqrt(2.0/VL);
    g_dct[i] = (float)(w * cos(3.141592653589793 * (t + 0.5) * k / (double)VL));
}

__global__ void transpose_postf(const float* __restrict__ poses) {
    int i = blockIdx.x * 256 + threadIdx.x;
    if (i >= INF*LDPF) return;
    int c = i / LDPF; int r = i - c*LDPF;
    int b = r / INN;  int tau = r - b*INN;
    g_postf[i] = poses[(size_t)b*144*INF + (size_t)tau*INF + c] * 1e-3f;
}

__global__ void pose_pfT(const float* __restrict__ poses) {
    int i = blockIdx.x * 256 + threadIdx.x;
    if (i >= NPOS1*160) return;
    int pos = i / 160, c = i - pos*160;
    int b = pos / INN, tau = pos - b*INN;
    float v = (c < INF) ? poses[(size_t)b*144*INF + (size_t)tau*INF + c] * 1e-3f : 0.f;
    __nv_bfloat16 h = __float2bfloat16(v);
    g_pfTh[i] = h;
    g_pfTl[i] = __float2bfloat16(v - __bfloat162float(h));
}

__global__ void pack_ws_all(const float* __restrict__ w1, const float* __restrict__ w2) {
    int i = blockIdx.x * 256 + threadIdx.x;
    const int NW1 = 512*960;
    if (i < NW1) {
        int o = i / 960, k = i - o*960;
        int j = k / 160, c = k - j*160;
        float v = (c < 135) ? w1[((size_t)o*135 + c)*6 + j] : 0.f;
        __nv_bfloat16 h = __float2bfloat16(v);
        g_w1h[i] = h;
        g_w1l[i] = __float2bfloat16(v - __bfloat162float(h));
    } else {
        int t = i - NW1;
        if (t >= 512*2560) return;
        int o = t / 2560, k = t - o*2560;
        int j = k / 512, c = k - j*512;
        float v = w2[((size_t)o*512 + c)*5 + j];
        __nv_bfloat16 h = __float2bfloat16(v);
        g_w2h[t] = h;
        g_w2l[t] = __float2bfloat16(v - __bfloat162float(h));
    }
}

__global__ void pack_w(const float* __restrict__ w, float* __restrict__ out,
                       int O, int C, int J, int CS) {
    int Kp = J * CS;
    int i = blockIdx.x * 256 + threadIdx.x;
    if (i >= O * Kp) return;
    int o = i / Kp, k = i - o*Kp;
    int j = k / CS, c = k - j*CS;
    out[i] = (c < C) ? w[((size_t)o*C + c)*J + j] : 0.f;
}

__global__ void pack_att(const float* __restrict__ a1, const float* __restrict__ ab,
                         const float* __restrict__ a7) {
    int i = blockIdx.x * 256 + threadIdx.x;
    if (i >= 6*135*144) return;
    int l = i / (135*144); int r = i - l*135*144;
    int m = r / 144, n = r - m*144;
    const float* src = (l == 0) ? a1 : (l <= 4 ? ab + (size_t)(l-1)*135*135 : a7);
    g_attT[i] = (n < 135) ? src[n*135 + m] : 0.f;
}

__global__ void pack_atts(const float* __restrict__ a1, const float* __restrict__ ab) {
    int i = blockIdx.x * 256 + threadIdx.x;
    if (i >= 5*144*160) return;
    int l = i / (144*160); int v = i - l*144*160;
    int r = v / 160, c = v - r*160;
    const float* src = (l == 0) ? a1 : ab + (size_t)(l-1)*135*135;
    float x = (r < 135 && c < 135) ? src[r*135 + c] : 0.f;
    __nv_bfloat16 h = __float2bfloat16(x);
    g_atth[i] = h;
    g_attl[i] = __float2bfloat16(x - __bfloat162float(h));
}

__global__ void pack_wt_split(const float* __restrict__ w) {
    int i = blockIdx.x * 256 + threadIdx.x;
    if (i >= 4*512*512) return;
    int l = i >> 18; int r = i & 262143;
    int gcol = r >> 9; int f = r & 511;
    float v = w[(size_t)l*262144 + (size_t)f*512 + gcol];
    __nv_bfloat16 h = __float2bfloat16(v);
    g_wth[i] = h;
    g_wtl[i] = __float2bfloat16(v - __bfloat162float(h));
}

// ======== wide merged-pass HMMA core: 128m x 256n tile, 3-stage ring ========
// buf (61440 B): Ah 0 | Al 10240 | Bh 20480 | Bl 40960. A 128x32 pitch80, B 256x32 pitch80.
#define HG3_SMEM (3*61440)

__device__ __forceinline__ void wide_compute(float acc[4][8][4], uint32_t bb,
                                             int wm, int wn, int lane) {
    uint32_t aA = bb + (wm + (lane & 15))*80 + (lane >> 4)*16;
    uint32_t aB = bb + 20480 + (wn + (lane & 7) + ((lane >> 4) & 1)*8)*80
                + ((lane >> 3) & 1)*16;
#pragma unroll
    for (int s = 0; s < 2; s++) {
        uint32_t ah[4][4], al[4][4], bh[4][4], bl[4][4];
#pragma unroll
        for (int mf = 0; mf < 4; mf++) ldsm4(ah[mf], aA + mf*1280 + s*32);
#pragma unroll
        for (int g = 0; g < 4; g++)  ldsm4(bh[g], aB + g*1280 + s*32);
#pragma unroll
        for (int mf = 0; mf < 4; mf++)
#pragma unroll
            for (int nf = 0; nf < 8; nf++)
                mma16816(acc[mf][nf], ah[mf], bh[nf>>1][(nf&1)*2], bh[nf>>1][(nf&1)*2+1]);
#pragma unroll
        for (int mf = 0; mf < 4; mf++) ldsm4(al[mf], aA + 10240 + mf*1280 + s*32);
#pragma unroll
        for (int mf = 0; mf < 4; mf++)
#pragma unroll
            for (int nf = 0; nf < 8; nf++)
                mma16816(acc[mf][nf], al[mf], bh[nf>>1][(nf&1)*2], bh[nf>>1][(nf&1)*2+1]);
#pragma unroll
        for (int g = 0; g < 4; g++)  ldsm4(bl[g], aB + 20480 + g*1280 + s*32);
#pragma unroll
        for (int mf = 0; mf < 4; mf++)
#pragma unroll
            for (int nf = 0; nf < 8; nf++)
                mma16816(acc[mf][nf], ah[mf], bl[nf>>1][(nf&1)*2], bl[nf>>1][(nf&1)*2+1]);
    }
}

// ---------------- HMMA GEMM (wide): t1 splits = A[M,512] @ W^T ----------------
__global__ void __launch_bounds__(256, 1) hgemm_gcb(
    const __nv_bfloat16* __restrict__ Ahi, const __nv_bfloat16* __restrict__ Alo,
    const __nv_bfloat16* __restrict__ Bhi, const __nv_bfloat16* __restrict__ Blo,
    __nv_bfloat16* __restrict__ Ch, __nv_bfloat16* __restrict__ Cl)
{
    extern __shared__ __align__(16) char SMC[];
    const int K = 512, N = 512;
    int tid = threadIdx.x, lane = tid & 31, warp = tid >> 5;
    int m0 = blockIdx.y * 128, n0 = blockIdx.x * 256;
    int wm = (warp >> 2) * 64, wn = (warp & 3) * 64;
    uint32_t sbase = smem_u32(SMC);

    float acc[4][8][4];
#pragma unroll
    for (int i = 0; i < 4; i++)
#pragma unroll
        for (int j = 0; j < 8; j++)
#pragma unroll
            for (int q = 0; q < 4; q++) acc[i][j][q] = 0.f;

    int arow = tid >> 1, acolB = (tid & 1) * 32;

    auto issue = [&](int c) {
        int k0 = c << 5;
        uint32_t dst = sbase + (uint32_t)(c % 3) * 61440;
        const char* a0 = (const char*)(Ahi + (size_t)(m0 + arow) * K + k0) + acolB;
        const char* a1 = (const char*)(Alo + (size_t)(m0 + arow) * K + k0) + acolB;
        uint32_t soA = arow*80 + acolB;
        cpa(dst + soA,              a0);
        cpa(dst + soA + 16,         a0 + 16);
        cpa(dst + 10240 + soA,      a1);
        cpa(dst + 10240 + soA + 16, a1 + 16);
        const char* b0 = (const char*)(Bhi + (size_t)(n0 + tid) * K + k0);
        const char* b1 = (const char*)(Blo + (size_t)(n0 + tid) * K + k0);
        uint32_t soB = tid*80;
#pragma unroll
        for (int seg = 0; seg < 4; seg++) {
            cpa(dst + 20480 + soB + seg*16, b0 + seg*16);
            cpa(dst + 40960 + soB + seg*16, b1 + seg*16);
        }
    };

    const int TOT = 16;
    issue(0); CP_COMMIT();
    issue(1); CP_COMMIT();
    for (int c = 0; c < TOT; c++) {
        if (c + 1 < TOT) CP_WAIT(1); else CP_WAIT(0);
        __syncthreads();
        if (c + 2 < TOT) { issue(c + 2); CP_COMMIT(); }
        wide_compute(acc, sbase + (uint32_t)(c % 3) * 61440, wm, wn, lane);
    }

#pragma unroll
    for (int mf = 0; mf < 4; mf++) {
        int m = m0 + wm + mf*16 + (lane >> 2);
#pragma unroll
        for (int nf = 0; nf < 8; nf++) {
            int n = n0 + wn + nf*8 + (lane & 3)*2;
#pragma unroll
            for (int rr = 0; rr < 2; rr++) {
                float v0 = acc[mf][nf][rr*2], v1 = acc[mf][nf][rr*2+1];
                size_t off = (size_t)(m + rr*8) * N + n;
                __nv_bfloat162 ph, pl;
                ph.x = __float2bfloat16(v0);
                pl.x = __float2bfloat16(v0 - __bfloat162float(ph.x));
                ph.y = __float2bfloat16(v1);
                pl.y = __float2bfloat16(v1 - __bfloat162float(ph.y));
                *(__nv_bfloat162*)&Ch[off] = ph;
                *(__nv_bfloat162*)&Cl[off] = pl;
            }
        }
    }
}

// ---------------- HMMA conv (wide, transposed gather) ----------------
template<int CS>
__global__ void __launch_bounds__(256, 1) hconv(
    const __nv_bfloat16* __restrict__ Ah, const __nv_bfloat16* __restrict__ Al,
    const __nv_bfloat16* __restrict__ Sh, const __nv_bfloat16* __restrict__ Sl,
    int Kp, int TW, int SW,
    __nv_bfloat16* __restrict__ OhT, __nv_bfloat16* __restrict__ OlT,
    int TWo, int SWo,
    float* __restrict__ Of, int ldf)
{
    extern __shared__ __align__(16) char SMC[];
    int tid = threadIdx.x, lane = tid & 31, warp = tid >> 5;
    int m0 = blockIdx.y * 128, n0 = blockIdx.x * 256;
    int wm = (warp >> 2) * 64, wn = (warp & 3) * 64;
    uint32_t sbase = smem_u32(SMC);

    float acc[4][8][4];
#pragma unroll
    for (int i = 0; i < 4; i++)
#pragma unroll
        for (int j = 0; j < 8; j++)
#pragma unroll
            for (int q = 0; q < 4; q++) acc[i][j][q] = 0.f;

    int arow = tid >> 1, acolB = (tid & 1) * 32;
    int gn = n0 + tid;
    int bidx = gn / TW;
    int scol = bidx * SW + (gn - bidx*TW);
    const int CPJ = CS / 32;

    auto issue = [&](int c) {
        int k0 = c << 5;
        uint32_t dst = sbase + (uint32_t)(c % 3) * 61440;
        const char* a0 = (const char*)(Ah + (size_t)(m0 + arow) * Kp + k0) + acolB;
        const char* a1 = (const char*)(Al + (size_t)(m0 + arow) * Kp + k0) + acolB;
        uint32_t soA = arow*80 + acolB;
        cpa(dst + soA,              a0);
        cpa(dst + soA + 16,         a0 + 16);
        cpa(dst + 10240 + soA,      a1);
        cpa(dst + 10240 + soA + 16, a1 + 16);
        int j = c / CPJ;
        int ccB = (c - j*CPJ) * 64;
        const char* b0 = (const char*)(Sh + (size_t)(scol + j) * CS) + ccB;
        const char* b1 = (const char*)(Sl + (size_t)(scol + j) * CS) + ccB;
        uint32_t soB = tid*80;
#pragma unroll
        for (int seg = 0; seg < 4; seg++) {
            cpa(dst + 20480 + soB + seg*16, b0 + seg*16);
            cpa(dst + 40960 + soB + seg*16, b1 + seg*16);
        }
    };

    int TOT = Kp >> 5;
    issue(0); CP_COMMIT();
    issue(1); CP_COMMIT();
    for (int c = 0; c < TOT; c++) {
        if (c + 1 < TOT) CP_WAIT(1); else CP_WAIT(0);
        __syncthreads();
        if (c + 2 < TOT) { issue(c + 2); CP_COMMIT(); }
        wide_compute(acc, sbase + (uint32_t)(c % 3) * 61440, wm, wn, lane);
    }

    if (Of) {
#pragma unroll
        for (int mf = 0; mf < 4; mf++) {
            int m = m0 + wm + mf*16 + (lane >> 2);
#pragma unroll
            for (int nf = 0; nf < 8; nf++) {
                int n = n0 + wn + nf*8 + (lane & 3)*2;
                *(float2*)&Of[(size_t)m * ldf + n] =
                    make_float2(fmaxf(acc[mf][nf][0], 0.f), fmaxf(acc[mf][nf][1], 0.f));
                *(float2*)&Of[(size_t)(m + 8) * ldf + n] =
                    make_float2(fmaxf(acc[mf][nf][2], 0.f), fmaxf(acc[mf][nf][3], 0.f));
            }
        }
    } else {
        __nv_bfloat16* stage = (__nv_bfloat16*)SMC;   // 256*136*2 = 69632 B
#pragma unroll
        for (int part = 0; part < 2; part++) {
            __syncthreads();
#pragma unroll
            for (int mf = 0; mf < 4; mf++)
#pragma unroll
                for (int nf = 0; nf < 8; nf++)
#pragma unroll
                    for (int q = 0; q < 4; q++) {
                        float v = fmaxf(acc[mf][nf][q], 0.f);
                        __nv_bfloat16 h = __float2bfloat16(v);
                        __nv_bfloat16 val = part ?
                            __float2bfloat16(v - __bfloat162float(h)) : h;
                        int nl = wn + nf*8 + (lane & 3)*2 + (q & 1);
                        int ml = wm + mf*16 + (lane >> 2) + ((q >= 2) ? 8 : 0);
                        stage[nl*136 + ml] = val;
                    }
            __syncthreads();
            __nv_bfloat16* D = part ? OlT : OhT;
            for (int u = tid; u < 4096; u += 256) {
                int r = u >> 4, seg = (u & 15) * 8;
                int gn2 = n0 + r;
                int b2 = gn2 / TWo;
                int grow = b2*SWo + (gn2 - b2*TWo);
                *(uint4*)(D + (size_t)grow*512 + m0 + seg) = *(const uint4*)(stage + r*136 + seg);
            }
        }
    }
}

// ---------------- HMMA attmix (unchanged from R8) ----------------
#define HG_SMEM (2*40960)
__global__ void __launch_bounds__(192, 2) hattmix(
    const __nv_bfloat16* __restrict__ Ah, const __nv_bfloat16* __restrict__ Al,
    const __nv_bfloat16* __restrict__ Bh, const __nv_bfloat16* __restrict__ Bl,
    float* __restrict__ Y, const float* __restrict__ bias,
    const float* __restrict__ gamma, const float* __restrict__ beta,
    const float* __restrict__ resid, int do_tanh,
    __nv_bfloat16* __restrict__ ohi, __nv_bfloat16* __restrict__ olo)
{
    extern __shared__ __align__(16) char SMC[];
    int tid = threadIdx.x, lane = tid & 31, warp = tid >> 5;
    int b = blockIdx.y, g0 = blockIdx.x * 128;
    int wm = (warp >> 1) * 48, wn = (warp & 1) * 64;
    uint32_t sbase = smem_u32(SMC);

    float acc[3][8][4];
#pragma unroll
    for (int i = 0; i < 3; i++)
#pragma unroll
        for (int j = 0; j < 8; j++)
#pragma unroll
            for (int q = 0; q < 4; q++) acc[i][j][q] = 0.f;

    auto issue = [&](int c) {
        int k0 = c << 5;
        uint32_t dst = sbase + (c & 1) * 40960;
#pragma unroll
        for (int i = 0; i < 6; i++) {
            int u = tid + i * 192;
            int s = u >= 576;
            int v = u - s * 576;
            int r = v >> 2, q = v & 3;
            const char* src = (const char*)(s ? Al : Ah) + ((size_t)r*160 + k0)*2 + q*16;
            cpa(dst + s*11520 + r*80 + q*16, src);
        }
        for (int u = tid; u < 1024; u += 192) {
            int s = u >= 512;
            int v = u - s * 512;
            int r = v >> 4, q = v & 15;
            const __nv_bfloat16* src = (s ? Bl : Bh)
                + (size_t)(b*135 + k0 + r) * 512 + g0 + q*8;
            cpa(dst + 23040 + s*8704 + r*272 + q*16, src);
        }
    };
    auto compute = [&](uint32_t bb) {
        uint32_t aA = bb + (wm + (lane & 15))*80 + (lane >> 4)*16;
        uint32_t aB = bb + 23040 + (lane & 15)*272 + (wn + (lane >> 4)*8)*2;
#pragma unroll
        for (int s = 0; s < 2; s++) {
            uint32_t ah[3][4], al[3][4], bh[4][4], bl[4][4];
#pragma unroll
            for (int mf = 0; mf < 3; mf++) ldsm4(ah[mf], aA + mf*(16*80) + s*32);
#pragma unroll
            for (int nb = 0; nb < 4; nb++) ldsm4t(bh[nb], aB + s*(16*272) + nb*32);
#pragma unroll
            for (int mf = 0; mf < 3; mf++)
#pragma unroll
                for (int nf = 0; nf < 8; nf++)
                    mma16816(acc[mf][nf], ah[mf], bh[nf>>1][(nf&1)*2], bh[nf>>1][(nf&1)*2+1]);
#pragma unroll
            for (int mf = 0; mf < 3; mf++) ldsm4(al[mf], aA + 11520 + mf*(16*80) + s*32);
#pragma unroll
            for (int mf = 0; mf < 3; mf++)
#pragma unroll
                for (int nf = 0; nf < 8; nf++)
                    mma16816(acc[mf][nf], al[mf], bh[nf>>1][(nf&1)*2], bh[nf>>1][(nf&1)*2+1]);
#pragma unroll
            for (int nb = 0; nb < 4; nb++) ldsm4t(bl[nb], aB + 8704 + s*(16*272) + nb*32);
#pragma unroll
            for (int mf = 0; mf < 3; mf++)
#pragma unroll
                for (int nf = 0; nf < 8; nf++)
                    mma16816(acc[mf][nf], ah[mf], bl[nf>>1][(nf&1)*2], bl[nf>>1][(nf&1)*2+1]);
        }
    };

    const int TOT = 5;
    issue(0); CP_COMMIT();
    for (int c = 0; c < TOT; c++) {
        if (c + 1 < TOT) { issue(c + 1); CP_COMMIT(); CP_WAIT(1); }
        else CP_WAIT(0);
        __syncthreads();
        compute(sbase + (c & 1) * 40960);
        __syncthreads();
    }

#pragma unroll
    for (int mf = 0; mf < 3; mf++) {
        int mb = wm + mf*16 + (lane >> 2);
#pragma unroll
        for (int rr = 0; rr < 2; rr++) {
            int m = mb + rr*8;
            if (m >= 135) continue;
            size_t row = ((size_t)b*135 + m) * 512;
#pragma unroll
            for (int nf = 0; nf < 8; nf++) {
                int n = g0 + wn + nf*8 + (lane & 3)*2;
                float v0 = acc[mf][nf][rr*2]     + bias[n];
                float v1 = acc[mf][nf][rr*2 + 1] + bias[n + 1];
                if (gamma) {
                    int gi = m*512 + n;
                    v0 = gamma[gi]*(v0*BN_SCALEF) + beta[gi];
                    v1 = gamma[gi+1]*(v1*BN_SCALEF) + beta[gi+1];
                }
                if (do_tanh) { v0 = tanhf(v0); v1 = tanhf(v1); }
                if (resid) { v0 += resid[row + n]; v1 += resid[row + n + 1]; }
                *(float2*)&Y[row + n] = make_float2(v0, v1);
                if (ohi) {
                    __nv_bfloat162 ph, pl;
                    ph.x = __float2bfloat16(v0);
                    pl.x = __float2bfloat16(v0 - __bfloat162float(ph.x));
                    ph.y = __float2bfloat16(v1);
                    pl.y = __float2bfloat16(v1 - __bfloat162float(ph.y));
                    *(__nv_bfloat162*)&ohi[row + n] = ph;
                    *(__nv_bfloat162*)&olo[row + n] = pl;
                }
            }
        }
    }
}

// ---------------- GEMM v1 (scalar FFMA2), optional bf16-split outputs ----------------
__global__ void __launch_bounds__(256, 2) gemm_v1(
    const float* __restrict__ A, const float* __restrict__ B, float* __restrict__ C,
    int M, int N, int K,
    __nv_bfloat16* __restrict__ oh, __nv_bfloat16* __restrict__ ol)
{
    __shared__ __align__(16) float As[2][16][132];
    __shared__ __align__(16) float Bs[2][16][128];
    int tid = threadIdx.x;
    int m0 = blockIdx.y * 128, n0 = blockIdx.x * 128;
    int tx4 = (tid & 15) * 4, ty4 = (tid >> 4) * 4;
    int arow = tid >> 1, akq = (tid & 1) * 8;
    int brow = tid >> 4, bcol = (tid & 15) * 8;
    ull acc[8][4];
#pragma unroll
    for (int i = 0; i < 8; i++)
#pragma unroll
        for (int j = 0; j < 4; j++) acc[i][j] = 0ULL;

    const float* Ap = A + (size_t)(m0 + arow) * K;
    const float4 z4 = make_float4(0.f,0.f,0.f,0.f);
    float4 ra0, ra1, rb0, rb1;

    auto loadT = [&](int k0) {
        int gk = k0 + akq;
        ra0 = (gk     < K) ? *(const float4*)(Ap + gk)     : z4;
        ra1 = (gk + 4 < K) ? *(const float4*)(Ap + gk + 4) : z4;
        int gkb = k0 + brow;
        rb0 = z4; rb1 = z4;
        if (gkb < K) {
            int gn = n0 + bcol;
            const float* Bp = B + (size_t)gkb * N + gn;
            if (gn + 7 < N) { rb0 = *(const float4*)Bp; rb1 = *(const float4*)(Bp + 4); }
            else {
                float t[8];
#pragma unroll
                for (int i = 0; i < 8; i++) t[i] = (gn + i < N) ? Bp[i] : 0.f;
                rb0 = make_float4(t[0],t[1],t[2],t[3]);
                rb1 = make_float4(t[4],t[5],t[6],t[7]);
            }
        }
    };
    auto storeT = [&](int buf) {
        As[buf][akq+0][arow] = ra0.x; As[buf][akq+1][arow] = ra0.y;
        As[buf][akq+2][arow] = ra0.z; As[buf][akq+3][arow] = ra0.w;
        As[buf][akq+4][arow] = ra1.x; As[buf][akq+5][arow] = ra1.y;
        As[buf][akq+6][arow] = ra1.z; As[buf][akq+7][arow] = ra1.w;
        *(float4*)&Bs[buf][brow][bcol]     = rb0;
        *(float4*)&Bs[buf][brow][bcol + 4] = rb1;
    };
    auto compute = [&](int buf) {
#pragma unroll
        for (int kk = 0; kk < 16; kk++) {
            float4 aL = *(const float4*)&As[buf][kk][ty4];
            float4 aH = *(const float4*)&As[buf][kk][ty4 + 64];
            longlong2 bL = *(const longlong2*)&Bs[buf][kk][tx4];
            longlong2 bH = *(const longlong2*)&Bs[buf][kk][tx4 + 64];
            ull bb0 = (ull)bL.x, bb1 = (ull)bL.y, bb2 = (ull)bH.x, bb3 = (ull)bH.y;
            float av[8] = {aL.x,aL.y,aL.z,aL.w,aH.x,aH.y,aH.z,aH.w};
#pragma unroll
            for (int i = 0; i < 8; i++) {
                ull aa = packf2(av[i]);
                ffma2(acc[i][0], aa, bb0);
                ffma2(acc[i][1], aa, bb1);
                ffma2(acc[i][2], aa, bb2);
                ffma2(acc[i][3], aa, bb3);
            }
        }
    };

    int nk = (K + 15) >> 4;
    loadT(0); storeT(0); __syncthreads();
    for (int kt = 0; kt < nk; kt++) {
        int buf = kt & 1;
        if (kt + 1 < nk) loadT((kt + 1) << 4);
        compute(buf);
        if (kt + 1 < nk) storeT(buf ^ 1);
        __syncthreads();
    }

#pragma unroll
    for (int i = 0; i < 8; i++) {
        int gm = m0 + ty4 + (i < 4 ? i : 60 + i);
#pragma unroll
        for (int j = 0; j < 4; j++) {
            float2 v = unpk(acc[i][j]);
            int gn = n0 + tx4 + (j < 2 ? 2*j : 60 + 2*j);
            size_t off = (size_t)gm * N + gn;
            if (C) {
                if (gn     < N) C[off]     = v.x;
                if (gn + 1 < N) C[off + 1] = v.y;
            }
            if (oh && gn + 1 < N) {
                __nv_bfloat162 ph, pl;
                ph.x = __float2bfloat16(v.x);
                pl.x = __float2bfloat16(v.x - __bfloat162float(ph.x));
                ph.y = __float2bfloat16(v.y);
                pl.y = __float2bfloat16(v.y - __bfloat162float(ph.y));
                *(__nv_bfloat162*)&oh[off] = ph;
                *(__nv_bfloat162*)&ol[off] = pl;
            }
        }
    }
}

// ---------------- conv GEMM (scalar, query branch) ----------------
template<int CS, int CSV>
__global__ void __launch_bounds__(256, 2) conv_gemm(
    const float* __restrict__ A, const float* __restrict__ src, float* __restrict__ C,
    int M, int N, int K, int LD, int TW, int SW, int WOFF,
    int ldc, int TWo, int SWo, int relu, int kchunk)
{
    __shared__ __align__(16) float As[2][16][132];
    __shared__ __align__(16) float Bs[2][16][128];
    int tid = threadIdx.x;
    int m0 = blockIdx.y * 128, n0 = blockIdx.x * 128;
    int tx4 = (tid & 15) * 4, ty4 = (tid >> 4) * 4;
    int arow = tid >> 1, akq = (tid & 1) * 8;
    int kbeg = blockIdx.z * kchunk;
    int kend = min(K, kbeg + kchunk);

    int nloc = tid & 127;
    int krow0 = (tid >> 7) * 8;
    int gn_b = n0 + nloc;
    int bidx = gn_b / TW;
    size_t bcolb = (size_t)bidx * SW + (gn_b - bidx*TW) + WOFF;

    ull acc[8][4];
#pragma unroll
    for (int i = 0; i < 8; i++)
#pragma unroll
        for (int j = 0; j < 4; j++) acc[i][j] = 0ULL;

    const float* Ap = A + (size_t)(m0 + arow) * K;
    const float4 z4 = make_float4(0.f,0.f,0.f,0.f);
    float4 ra0, ra1; float rb[8];

    auto loadT = [&](int k0) {
        int gk = k0 + akq;
        ra0 = (gk     < kend) ? *(const float4*)(Ap + gk)     : z4;
        ra1 = (gk + 4 < kend) ? *(const float4*)(Ap + gk + 4) : z4;
#pragma unroll
        for (int i = 0; i < 8; i++) {
            int gkk = k0 + krow0 + i;
            float v = 0.f;
            if (gkk < kend && gn_b < N) {
                int j = gkk / CS; int c = gkk - j*CS;
                if (c < CSV) v = src[(size_t)c*LD + bcolb + j];
            }
            rb[i] = v;
        }
    };
    auto storeT = [&](int buf) {
        As[buf][akq+0][arow] = ra0.x; As[buf][akq+1][arow] = ra0.y;
        As[buf][akq+2][arow] = ra0.z; As[buf][akq+3][arow] = ra0.w;
        As[buf][akq+4][arow] = ra1.x; As[buf][akq+5][arow] = ra1.y;
        As[buf][akq+6][arow] = ra1.z; As[buf][akq+7][arow] = ra1.w;
#pragma unroll
        for (int i = 0; i < 8; i++) Bs[buf][krow0+i][nloc] = rb[i];
    };
    auto compute = [&](int buf) {
#pragma unroll
        for (int kk = 0; kk < 16; kk++) {
            float4 aL = *(const float4*)&As[buf][kk][ty4];
            float4 aH = *(const float4*)&As[buf][kk][ty4 + 64];
            longlong2 bL = *(const longlong2*)&Bs[buf][kk][tx4];
            longlong2 bH = *(const longlong2*)&Bs[buf][kk][tx4 + 64];
            ull bb0 = (ull)bL.x, bb1 = (ull)bL.y, bb2 = (ull)bH.x, bb3 = (ull)bH.y;
            float av[8] = {aL.x,aL.y,aL.z,aL.w,aH.x,aH.y,aH.z,aH.w};
#pragma unroll
            for (int i = 0; i < 8; i++) {
                ull aa = packf2(av[i]);
                ffma2(acc[i][0], aa, bb0);
                ffma2(acc[i][1], aa, bb1);
                ffma2(acc[i][2], aa, bb2);
                ffma2(acc[i][3], aa, bb3);
            }
        }
    };

    int nk = (kend - kbeg + 15) >> 4;
    loadT(kbeg); storeT(0); __syncthreads();
    for (int kt = 0; kt < nk; kt++) {
        int buf = kt & 1;
        if (kt + 1 < nk) loadT(kbeg + ((kt + 1) << 4));
        compute(buf);
        if (kt + 1 < nk) storeT(buf ^ 1);
        __syncthreads();
    }

    C += (size_t)blockIdx.z * M * N;
#pragma unroll
    for (int i = 0; i < 8; i++) {
        int gm = m0 + ty4 + (i < 4 ? i : 60 + i);
        float* Cp = C + (size_t)gm * ldc;
#pragma unroll
        for (int j = 0; j < 4; j++) {
            float2 v = unpk(acc[i][j]);
            int gn = n0 + tx4 + (j < 2 ? 2*j : 60 + 2*j);
            float vx = relu ? fmaxf(v.x, 0.f) : v.x;
            float vy = relu ? fmaxf(v.y, 0.f) : v.y;
            if (gn < N) {
                int col = TWo ? (gn/TWo)*SWo + gn%TWo : gn;
                Cp[col] = vx;
            }
            if (gn + 1 < N) {
                int g1 = gn + 1;
                int col = TWo ? (g1/TWo)*SWo + g1%TWo : g1;
                Cp[col] = vy;
            }
        }
    }
}

__global__ void reduce_remap(const float* __restrict__ part, float* __restrict__ C,
                             int M, int N, int S, int ldo, int TWo, int SWo) {
    int i = blockIdx.x * 256 + threadIdx.x;
    if (i >= M * N) return;
    int m = i / N, n = i - m*N;
    float a = 0.f;
    for (int s = 0; s < S; s++) a += part[(size_t)s*M*N + i];
    int col = TWo ? (n/TWo)*SWo + n%TWo : n;
    C[(size_t)m*ldo + col] = fmaxf(a, 0.f);
}

// ---------------- attention scores + normalization ----------------
__global__ void att_kernel() {
    int b = blockIdx.x, t = threadIdx.x;
    float s = 0.f;
    if (t < VN) {
        for (int o = 0; o < 512; o++)
            s += g_qryf[o*N2Q + b] * g_keyf[(size_t)o*N2K + b*VN + t];
        s += 1e-15f;
    }
    __shared__ float sm[128];
    sm[t] = (t < VN) ? s : 0.f;
    __syncthreads();
    for (int off = 64; off > 0; off >>= 1) {
        if (t < off) sm[t] += sm[t + off];
        __syncthreads();
    }
    if (t < VN) g_att[b*VN + t] = s / sm[0];
}

// ---------------- build x ----------------
__global__ void build_x(const float* __restrict__ poses) {
    int b = blockIdx.x, tid = threadIdx.x;
    __shared__ float s_att[VN];
    __shared__ float s_ws[VL*INF];
    __shared__ float s_dct[VL*VL];
    if (tid < VN) s_att[tid] = g_att[b*VN + tid];
    for (int i = tid; i < VL*VL; i += 256) s_dct[i] = g_dct[i];
    __syncthreads();
    const float* pb = poses + (size_t)b * 144 * INF;
    for (int i = tid; i < VL*INF; i += 256) {
        int t = i / INF, f = i - t*INF;
        float acc = 0.f;
        for (int v = 0; v < VN; v++) acc += s_att[v] * pb[(v + t)*INF + f];
        s_ws[i] = acc;
    }
    __syncthreads();
    float* xb = g_x + (size_t)b * INF * 68;
    for (int i = tid; i < INF*VL; i += 256) {
        int f = i / VL, k = i - f*VL;
        float a0 = 0.f, a1 = 0.f;
        for (int t = 0; t < VL; t++) {
            float d = s_dct[k*VL + t];
            int pt = (t < KQ) ? (110 + t) : 119;
            a0 += d * pb[pt*INF + f];
            a1 += d * s_ws[t*INF + f];
        }
        xb[f*68 + k]      = a0;
        xb[f*68 + 34 + k] = a1;
    }
}

// ---------------- scalar att-mix (gc7 only) ----------------
__global__ void __launch_bounds__(256, 2) attmix(
    const float* __restrict__ AT, const float* __restrict__ Bm, float* __restrict__ Cm,
    int N, const float* __restrict__ bias,
    const float* __restrict__ resid)
{
    __shared__ __align__(16) float Asm[27][148];
    int tid = threadIdx.x;
    int b = blockIdx.y;
    int n0 = blockIdx.x * 128;
    int colg = tid & 63;
    int grp  = tid >> 6;
    int nbase = grp * 36;
    int col0 = n0 + colg, col1 = col0 + 64;
    bool c0 = col0 < N, c1 = col1 < N;
    ull accA[18], accB[18];
#pragma unroll
    for (int i = 0; i < 18; i++) { accA[i] = 0ULL; accB[i] = 0ULL; }
    const float* Bb = Bm + (size_t)b * 135 * N;

    for (int mc = 0; mc < 135; mc += 27) {
        __syncthreads();
        for (int i = tid; i < 27*144; i += 256) {
            int mm = i / 144, n = i - mm*144;
            Asm[mm][n] = AT[(mc + mm)*144 + n];
        }
        __syncthreads();
        for (int mm = 0; mm < 27; mm++) {
            size_t off = (size_t)(mc + mm) * N;
            float b0 = c0 ? Bb[off + col0] : 0.f;
            float b1 = c1 ? Bb[off + col1] : 0.f;
            ull bb0 = packf2(b0), bb1 = packf2(b1);
            const longlong2* ap = (const longlong2*)&Asm[mm][nbase];
#pragma unroll
            for (int i = 0; i < 9; i++) {
                longlong2 av = ap[i];
                ffma2(accA[2*i],   (ull)av.x, bb0);
                ffma2(accB[2*i],   (ull)av.x, bb1);
                ffma2(accA[2*i+1], (ull)av.y, bb0);
                ffma2(accB[2*i+1], (ull)av.y, bb1);
            }
        }
    }

    float bias0 = c0 ? bias[col0] : 0.f;
    float bias1 = c1 ? bias[col1] : 0.f;
    size_t crow = (size_t)b * 135 * N;
#pragma unroll
    for (int i = 0; i < 18; i++) {
        float2 vA = unpk(accA[i]);
        float2 vB = unpk(accB[i]);
#pragma unroll
        for (int r = 0; r < 2; r++) {
            int n = nbase + 2*i + r;
            if (n >= 135) continue;
            float va = (r == 0) ? vA.x : vA.y;
            float vb = (r == 0) ? vB.x : vB.y;
            size_t rowoff = crow + (size_t)n * N;
            if (c0) Cm[rowoff + col0] = va + bias0 + (resid ? resid[rowoff + col0] : 0.f);
            if (c1) Cm[rowoff + col1] = vb + bias1 + (resid ? resid[rowoff + col1] : 0.f);
        }
    }
}

// ---------------- final IDCT ----------------
__global__ void final_idct(float* __restrict__ out) {
    int i = blockIdx.x * 256 + threadIdx.x;
    if (i >= NB*OUTN*INF) return;
    int f = i % INF; int r = i / INF;
    int ti = r % OUTN; int b = r / OUTN;
    const float* yb = g_t2 + (size_t)b*INF*68 + (size_t)f*68;
    int t = KQ + ti;
    float acc = 0.f;
    for (int k = 0; k < DCTN; k++) acc += g_dct[k*VL + t] * yb[k];
    out[i] = acc;
}

// ---------------- launch ----------------
extern "C" void kernel_launch(void* const* d_in, const int* in_sizes, int n_in,
                              void* d_out, int out_size)
{
    (void)in_sizes; (void)n_in; (void)out_size;
    const float* poses   = (const float*)d_in[0];
    const float* qw1     = (const float*)d_in[1];
    const float* qw2     = (const float*)d_in[2];
    const float* kw1     = (const float*)d_in[3];
    const float* kw2     = (const float*)d_in[4];
    const float* gc1_att = (const float*)d_in[5];
    const float* gc1_w   = (const float*)d_in[6];
    const float* gc1_b   = (const float*)d_in[7];
    const float* bn1_g   = (const float*)d_in[8];
    const float* bn1_b   = (const float*)d_in[9];
    const float* gcb_att = (const float*)d_in[10];
    const float* gcb_w   = (const float*)d_in[11];
    const float* gcb_b   = (const float*)d_in[12];
    const float* gcb_g   = (const float*)d_in[13];
    const float* gcb_beta= (const float*)d_in[14];
    const float* gc7_att = (const float*)d_in[15];
    const float* gc7_w   = (const float*)d_in[16];
    const float* gc7_b   = (const float*)d_in[17];
    float* out = (float*)d_out;

    void *pv;
    cudaGetSymbolAddress(&pv, g_postf); float* postf = (float*)pv;
    cudaGetSymbolAddress(&pv, g_pfTh);  __nv_bfloat16* pfTh = (__nv_bfloat16*)pv;
    cudaGetSymbolAddress(&pv, g_pfTl);  __nv_bfloat16* pfTl = (__nv_bfloat16*)pv;
    cudaGetSymbolAddress(&pv, g_w1h);   __nv_bfloat16* w1h = (__nv_bfloat16*)pv;
    cudaGetSymbolAddress(&pv, g_w1l);   __nv_bfloat16* w1l = (__nv_bfloat16*)pv;
    cudaGetSymbolAddress(&pv, g_w2h);   __nv_bfloat16* w2h = (__nv_bfloat16*)pv;
    cudaGetSymbolAddress(&pv, g_w2l);   __nv_bfloat16* w2l = (__nv_bfloat16*)pv;
    cudaGetSymbolAddress(&pv, g_h1kTh); __nv_bfloat16* h1kTh = (__nv_bfloat16*)pv;
    cudaGetSymbolAddress(&pv, g_h1kTl); __nv_bfloat16* h1kTl = (__nv_bfloat16*)pv;
    cudaGetSymbolAddress(&pv, g_q1p);   float* q1p   = (float*)pv;
    cudaGetSymbolAddress(&pv, g_q2p);   float* q2p   = (float*)pv;
    cudaGetSymbolAddress(&pv, g_h1q);   float* h1q   = (float*)pv;
    cudaGetSymbolAddress(&pv, g_keyf);  float* keyf  = (float*)pv;
    cudaGetSymbolAddress(&pv, g_qryf);  float* qryf  = (float*)pv;
    cudaGetSymbolAddress(&pv, g_part);  float* part  = (float*)pv;
    cudaGetSymbolAddress(&pv, g_attT);  float* attT  = (float*)pv;
    cudaGetSymbolAddress(&pv, g_atth);  __nv_bfloat16* atth = (__nv_bfloat16*)pv;
    cudaGetSymbolAddress(&pv, g_attl);  __nv_bfloat16* attl = (__nv_bfloat16*)pv;
    cudaGetSymbolAddress(&pv, g_x);     float* xp    = (float*)pv;
    cudaGetSymbolAddress(&pv, g_t1);    float* t1p   = (float*)pv;
    cudaGetSymbolAddress(&pv, g_t1h);   __nv_bfloat16* t1h = (__nv_bfloat16*)pv;
    cudaGetSymbolAddress(&pv, g_t1l);   __nv_bfloat16* t1l = (__nv_bfloat16*)pv;
    cudaGetSymbolAddress(&pv, g_t2);    float* t2p   = (float*)pv;
    cudaGetSymbolAddress(&pv, g_y);     float* yp    = (float*)pv;
    cudaGetSymbolAddress(&pv, g_s0h);   __nv_bfloat16* s0h = (__nv_bfloat16*)pv;
    cudaGetSymbolAddress(&pv, g_s0l);   __nv_bfloat16* s0l = (__nv_bfloat16*)pv;
    cudaGetSymbolAddress(&pv, g_s1h);   __nv_bfloat16* s1h = (__nv_bfloat16*)pv;
    cudaGetSymbolAddress(&pv, g_s1l);   __nv_bfloat16* s1l = (__nv_bfloat16*)pv;
    cudaGetSymbolAddress(&pv, g_wth);   __nv_bfloat16* wth = (__nv_bfloat16*)pv;
    cudaGetSymbolAddress(&pv, g_wtl);   __nv_bfloat16* wtl = (__nv_bfloat16*)pv;

    cudaFuncSetAttribute(hgemm_gcb, cudaFuncAttributeMaxDynamicSharedMemorySize, HG3_SMEM);
    cudaFuncSetAttribute(hconv<160>, cudaFuncAttributeMaxDynamicSharedMemorySize, HG3_SMEM);
    cudaFuncSetAttribute(hconv<512>, cudaFuncAttributeMaxDynamicSharedMemorySize, HG3_SMEM);
    cudaFuncSetAttribute(hattmix, cudaFuncAttributeMaxDynamicSharedMemorySize, HG_SMEM);

    // --- launch #4 = hconv<512> (the ncu-profiled slot) ---
    pack_ws_all<<<(512*3520 + 255)/256, 256>>>(kw1, kw2);                 // 1
    pose_pfT<<<(NPOS1*160 + 255)/256, 256>>>(poses);                      // 2
    hconv<160><<<dim3(91, 4), 256, HG3_SMEM>>>(w1h, w1l, pfTh, pfTl,      // 3
        960, 91, 120, h1kTh, h1kTl, 91, 96, (float*)0, 0);
    hconv<512><<<dim3(87, 4), 256, HG3_SMEM>>>(w2h, w2l, h1kTh, h1kTl,    // 4 <- profiled
        2560, 87, 96, (__nv_bfloat16*)0, (__nv_bfloat16*)0, 0, 0, keyf, N2K);

    init_dct<<<5, 256>>>();
    transpose_postf<<<(INF*LDPF + 255)/256, 256>>>(poses);

    // query branch (scalar, small)
    pack_w<<<(512*816 + 255)/256, 256>>>(qw1, q1p, 512, 135, 6, 136);
    conv_gemm<136,135><<<dim3(N1Q/128, 4, 3), 256>>>(q1p, postf, part,
        512, N1Q, 816, LDPF, 5, 120, 110, N1Q, 0, 0, 0, 272);
    reduce_remap<<<(512*N1Q + 255)/256, 256>>>(part, h1q, 512, N1Q, 3, LDQ1, 5, 12);
    pack_w<<<(512*2560 + 255)/256, 256>>>(qw2, q2p, 512, 512, 5, 512);
    conv_gemm<512,512><<<dim3(N2Q/128, 4, 10), 256>>>(q2p, h1q, part,
        512, N2Q, 2560, LDQ1, 1, 12, 0, N2Q, 0, 0, 0, 256);
    reduce_remap<<<(512*N2Q + 255)/256, 256>>>(part, qryf, 512, N2Q, 10, N2Q, 0, 0);

    pack_att<<<(6*135*144 + 255)/256, 256>>>(gc1_att, gcb_att, gc7_att);
    pack_atts<<<(5*144*160 + 255)/256, 256>>>(gc1_att, gcb_att);
    pack_wt_split<<<(4*512*512 + 255)/256, 256>>>(gcb_w);
    att_kernel<<<NB, 128>>>();
    build_x<<<NB, 256>>>(poses);

    // gc1: scalar GEMM -> t1 splits; HMMA attmix -> yp + s0 splits
    gemm_v1<<<dim3(4, 270), 256>>>(xp, gc1_w, (float*)0, 34560, 512, 68, t1h, t1l);
    hattmix<<<dim3(4, NB), 192, HG_SMEM>>>(atth, attl, t1h, t1l, yp,
        gc1_b, bn1_g, bn1_b, (const float*)0, 1, s0h, s0l);

    // 4 gcb layers: wide HMMA GEMM (emits t1 splits) + HMMA attmix
    for (int l = 0; l < 4; l++) {
        const __nv_bfloat16* ah = (l & 1) ? s1h : s0h;
        const __nv_bfloat16* al = (l & 1) ? s1l : s0l;
        __nv_bfloat16* oh = (l == 3) ? (__nv_bfloat16*)0 : ((l & 1) ? s0h : s1h);
        __nv_bfloat16* ol = (l == 3) ? (__nv_bfloat16*)0 : ((l & 1) ? s0l : s1l);
        float*       o   = (l & 1) ? yp  : t2p;
        const float* res = (l & 1) ? yp  : (const float*)0;
        hgemm_gcb<<<dim3(2, 270), 256, HG3_SMEM>>>(ah, al,
            wth + (size_t)l*262144, wtl + (size_t)l*262144, t1h, t1l);
        hattmix<<<dim3(4, NB), 192, HG_SMEM>>>(
            atth + (size_t)(1+l)*144*160, attl + (size_t)(1+l)*144*160,
            t1h, t1l, o,
            gcb_b + (size_t)l*512,
            gcb_g + (size_t)l*69120, gcb_beta + (size_t)l*69120,
            res, 1, oh, ol);
    }

    // gc7 (scalar) + scalar attmix + residual x
    gemm_v1<<<dim3(1, 270), 256>>>(yp, gc7_w, t1p, 34560, 68, 512,
                                   (__nv_bfloat16*)0, (__nv_bfloat16*)0);
    attmix<<<dim3(1, NB), 256>>>(attT + (size_t)5*135*144, t1p, t2p, 68, gc7_b, xp);

    final_idct<<<(NB*OUTN*INF + 255)/256, 256>>>(out);
}

// round 10
// speedup vs baseline: 1.1896x; 1.1896x over previous
#include <cuda_runtime.h>
#include <cuda_bf16.h>
#include <math.h>
#include <stdint.h>

typedef unsigned long long ull;

// ---------------- problem constants ----------------
#define NB    256
#define INF   135
#define INN   120
#define OUTN  24
#define KQ    10
#define VL    34
#define VN    87
#define DCTN  34

#define N1K   23296
#define N2K   22272
#define N1Q   1280
#define N2Q   256

#define LDPF  30720
#define LDQ1  3072
#define NPOS1 30720
#define NPOS2 24576

#define BN_SCALEF 0.9999950000374997f

// ---------------- scratch ----------------
__device__ __align__(128) float g_postf[INF*LDPF];
__device__ __align__(128) __nv_bfloat16 g_pfTh[NPOS1*160];
__device__ __align__(128) __nv_bfloat16 g_pfTl[NPOS1*160];
__device__ __align__(128) __nv_bfloat16 g_w1h[512*960];
__device__ __align__(128) __nv_bfloat16 g_w1l[512*960];
__device__ __align__(128) __nv_bfloat16 g_w2h[512*2560];
__device__ __align__(128) __nv_bfloat16 g_w2l[512*2560];
__device__ __align__(128) __nv_bfloat16 g_h1kTh[NPOS2*512];
__device__ __align__(128) __nv_bfloat16 g_h1kTl[NPOS2*512];
__device__ __align__(128) float g_q1p[512*816];
__device__ __align__(128) float g_q2p[512*2560];
__device__ __align__(128) float g_h1q[512*LDQ1];
__device__ __align__(128) float g_keyf[512*N2K];
__device__ __align__(128) float g_qryf[512*N2Q];
__device__ __align__(128) float g_part[3*512*1280];
__device__ __align__(128) float g_att[NB*VN];
__device__ __align__(128) float g_attT[6*135*144];
__device__ __align__(128) __nv_bfloat16 g_atth[5*144*160];
__device__ __align__(128) __nv_bfloat16 g_attl[5*144*160];
__device__ __align__(128) float g_x[NB*INF*68];
__device__ __align__(128) __nv_bfloat16 g_xh[34560*96];
__device__ __align__(128) __nv_bfloat16 g_xl[34560*96];
__device__ __align__(128) __nv_bfloat16 g_wt1h[512*96];
__device__ __align__(128) __nv_bfloat16 g_wt1l[512*96];
__device__ __align__(128) __nv_bfloat16 g_wt7h[128*512];
__device__ __align__(128) __nv_bfloat16 g_wt7l[128*512];
__device__ __align__(128) float g_t1[34560*68];
__device__ __align__(128) __nv_bfloat16 g_t1h[(34560+192)*512];
__device__ __align__(128) __nv_bfloat16 g_t1l[(34560+192)*512];
__device__ __align__(128) float g_t2[34560*512];
__device__ __align__(128) float g_y[34560*512];
__device__ __align__(128) float g_dct[VL*VL];
__device__ __align__(128) __nv_bfloat16 g_s0h[(34560+192)*512];
__device__ __align__(128) __nv_bfloat16 g_s0l[(34560+192)*512];
__device__ __align__(128) __nv_bfloat16 g_s1h[(34560+192)*512];
__device__ __align__(128) __nv_bfloat16 g_s1l[(34560+192)*512];
__device__ __align__(128) __nv_bfloat16 g_wth[4*512*512];
__device__ __align__(128) __nv_bfloat16 g_wtl[4*512*512];

// ---------------- f32x2 helpers ----------------
__device__ __forceinline__ ull packf2(float v) {
    ull r; asm("mov.b64 %0, {%1, %2};" : "=l"(r) : "f"(v), "f"(v)); return r;
}
__device__ __forceinline__ void ffma2(ull &d, ull a, ull b) {
    asm("fma.rn.f32x2 %0, %1, %2, %0;" : "+l"(d) : "l"(a), "l"(b));
}
__device__ __forceinline__ float2 unpk(ull v) {
    float2 r; asm("mov.b64 {%0, %1}, %2;" : "=f"(r.x), "=f"(r.y) : "l"(v)); return r;
}

// ---------------- MMA / async helpers ----------------
__device__ __forceinline__ uint32_t smem_u32(const void* p) {
    uint32_t a;
    asm("{ .reg .u64 t; cvta.to.shared.u64 t, %1; cvt.u32.u64 %0, t; }" : "=r"(a) : "l"(p));
    return a;
}
__device__ __forceinline__ void ldsm4(uint32_t* r, uint32_t addr) {
    asm volatile("ldmatrix.sync.aligned.m8n8.x4.shared.b16 {%0,%1,%2,%3}, [%4];"
        : "=r"(r[0]), "=r"(r[1]), "=r"(r[2]), "=r"(r[3]) : "r"(addr));
}
__device__ __forceinline__ void ldsm4t(uint32_t* r, uint32_t addr) {
    asm volatile("ldmatrix.sync.aligned.m8n8.x4.trans.shared.b16 {%0,%1,%2,%3}, [%4];"
        : "=r"(r[0]), "=r"(r[1]), "=r"(r[2]), "=r"(r[3]) : "r"(addr));
}
__device__ __forceinline__ void mma16816(float* c, const uint32_t* a,
                                         uint32_t b0, uint32_t b1) {
    asm volatile("mma.sync.aligned.m16n8k16.row.col.f32.bf16.bf16.f32 "
        "{%0,%1,%2,%3}, {%4,%5,%6,%7}, {%8,%9}, {%0,%1,%2,%3};"
        : "+f"(c[0]), "+f"(c[1]), "+f"(c[2]), "+f"(c[3])
        : "r"(a[0]), "r"(a[1]), "r"(a[2]), "r"(a[3]), "r"(b0), "r"(b1));
}
__device__ __forceinline__ void cpa(uint32_t s, const void* g) {
    asm volatile("cp.async.cg.shared.global [%0], [%1], 16;" :: "r"(s), "l"(g));
}
#define CP_COMMIT() asm volatile("cp.async.commit_group;" ::: "memory")
#define CP_WAIT(n)  asm volatile("cp.async.wait_group %0;" :: "n"(n) : "memory")

// ---------------- small setup kernels ----------------
__global__ void init_dct() {
    int i = blockIdx.x * 256 + threadIdx.x;
    if (i >= VL*VL) return;
    int k = i / VL, t = i % VL;
    double w = (k == 0) ? sqrt(1.0/VL) : sqrt(2.0/VL);
    g_dct[i] = (float)(w * cos(3.141592653589793 * (t + 0.5) * k / (double)VL));
}

__global__ void transpose_postf(const float* __restrict__ poses) {
    int i = blockIdx.x * 256 + threadIdx.x;
    if (i >= INF*LDPF) return;
    int c = i / LDPF; int r = i - c*LDPF;
    int b = r / INN;  int tau = r - b*INN;
    g_postf[i] = poses[(size_t)b*144*INF + (size_t)tau*INF + c] * 1e-3f;
}

__global__ void pose_pfT(const float* __restrict__ poses) {
    int i = blockIdx.x * 256 + threadIdx.x;
    if (i >= NPOS1*160) return;
    int pos = i / 160, c = i - pos*160;
    int b = pos / INN, tau = pos - b*INN;
    float v = (c < INF) ? poses[(size_t)b*144*INF + (size_t)tau*INF + c] * 1e-3f : 0.f;
    __nv_bfloat16 h = __float2bfloat16(v);
    g_pfTh[i] = h;
    g_pfTl[i] = __float2bfloat16(v - __bfloat162float(h));
}

__global__ void pack_ws_all(const float* __restrict__ w1, const float* __restrict__ w2) {
    int i = blockIdx.x * 256 + threadIdx.x;
    const int NW1 = 512*960;
    if (i < NW1) {
        int o = i / 960, k = i - o*960;
        int j = k / 160, c = k - j*160;
        float v = (c < 135) ? w1[((size_t)o*135 + c)*6 + j] : 0.f;
        __nv_bfloat16 h = __float2bfloat16(v);
        g_w1h[i] = h;
        g_w1l[i] = __float2bfloat16(v - __bfloat162float(h));
    } else {
        int t = i - NW1;
        if (t >= 512*2560) return;
        int o = t / 2560, k = t - o*2560;
        int j = k / 512, c = k - j*512;
        float v = w2[((size_t)o*512 + c)*5 + j];
        __nv_bfloat16 h = __float2bfloat16(v);
        g_w2h[t] = h;
        g_w2l[t] = __float2bfloat16(v - __bfloat162float(h));
    }
}

__global__ void pack_w(const float* __restrict__ w, float* __restrict__ out,
                       int O, int C, int J, int CS) {
    int Kp = J * CS;
    int i = blockIdx.x * 256 + threadIdx.x;
    if (i >= O * Kp) return;
    int o = i / Kp, k = i - o*Kp;
    int j = k / CS, c = k - j*CS;
    out[i] = (c < C) ? w[((size_t)o*C + c)*J + j] : 0.f;
}

__global__ void pack_att(const float* __restrict__ a1, const float* __restrict__ ab,
                         const float* __restrict__ a7) {
    int i = blockIdx.x * 256 + threadIdx.x;
    if (i >= 6*135*144) return;
    int l = i / (135*144); int r = i - l*135*144;
    int m = r / 144, n = r - m*144;
    const float* src = (l == 0) ? a1 : (l <= 4 ? ab + (size_t)(l-1)*135*135 : a7);
    g_attT[i] = (n < 135) ? src[n*135 + m] : 0.f;
}

__global__ void pack_atts(const float* __restrict__ a1, const float* __restrict__ ab) {
    int i = blockIdx.x * 256 + threadIdx.x;
    if (i >= 5*144*160) return;
    int l = i / (144*160); int v = i - l*144*160;
    int r = v / 160, c = v - r*160;
    const float* src = (l == 0) ? a1 : ab + (size_t)(l-1)*135*135;
    float x = (r < 135 && c < 135) ? src[r*135 + c] : 0.f;
    __nv_bfloat16 h = __float2bfloat16(x);
    g_atth[i] = h;
    g_attl[i] = __float2bfloat16(x - __bfloat162float(h));
}

__global__ void pack_wt_split(const float* __restrict__ w) {
    int i = blockIdx.x * 256 + threadIdx.x;
    if (i >= 4*512*512) return;
    int l = i >> 18; int r = i & 262143;
    int gcol = r >> 9; int f = r & 511;
    float v = w[(size_t)l*262144 + (size_t)f*512 + gcol];
    __nv_bfloat16 h = __float2bfloat16(v);
    g_wth[i] = h;
    g_wtl[i] = __float2bfloat16(v - __bfloat162float(h));
}

// gc1_w [68][512] -> wt1 splits [512][96]; gc7_w [512][68] -> wt7 splits [128][512]
__global__ void pack_wt17(const float* __restrict__ w1, const float* __restrict__ w7) {
    int i = blockIdx.x * 256 + threadIdx.x;
    const int N1 = 512*96;
    if (i < N1) {
        int n = i / 96, k = i - n*96;
        float v = (k < 68) ? w1[(size_t)k*512 + n] : 0.f;
        __nv_bfloat16 h = __float2bfloat16(v);
        g_wt1h[i] = h;
        g_wt1l[i] = __float2bfloat16(v - __bfloat162float(h));
    } else {
        int t = i - N1;
        if (t >= 128*512) return;
        int n = t / 512, k = t - n*512;
        float v = (n < 68) ? w7[(size_t)k*68 + n] : 0.f;
        __nv_bfloat16 h = __float2bfloat16(v);
        g_wt7h[t] = h;
        g_wt7l[t] = __float2bfloat16(v - __bfloat162float(h));
    }
}

// ---------------- generalized narrow HMMA GEMM (R8 core) ----------------
// C = A[M x KpA-strided] @ B^T (B rows n, stride KpB). TOT = K/32 chunks.
// Out: bf16 splits Ch/Cl (ld 512) OR fp32 Cf (ld Nv, col guard n < Nv).
#define HG_SMEM (2*40960)
__global__ void __launch_bounds__(256, 2) hgemm_gen(
    const __nv_bfloat16* __restrict__ Ahi, const __nv_bfloat16* __restrict__ Alo, int KpA,
    const __nv_bfloat16* __restrict__ Bhi, const __nv_bfloat16* __restrict__ Blo, int KpB,
    int TOT,
    __nv_bfloat16* __restrict__ Ch, __nv_bfloat16* __restrict__ Cl,
    float* __restrict__ Cf, int Nv)
{
    extern __shared__ __align__(16) char SMC[];
    int tid = threadIdx.x, lane = tid & 31, warp = tid >> 5;
    int m0 = blockIdx.y * 128, n0 = blockIdx.x * 128;
    int wm = (warp >> 2) * 64, wn = (warp & 3) * 32;
    uint32_t sbase = smem_u32(SMC);

    float acc[4][4][4];
#pragma unroll
    for (int i = 0; i < 4; i++)
#pragma unroll
        for (int j = 0; j < 4; j++)
#pragma unroll
            for (int q = 0; q < 4; q++) acc[i][j][q] = 0.f;

    int lrow = tid >> 2, lcolB = (tid & 3) * 16;

    auto issue = [&](int c) {
        int k0 = c << 5;
        uint32_t dst = sbase + (c & 1) * 40960;
        const char* a0 = (const char*)(Ahi + (size_t)(m0 + lrow) * KpA + k0) + lcolB;
        const char* a1 = (const char*)(Alo + (size_t)(m0 + lrow) * KpA + k0) + lcolB;
        const char* b0 = (const char*)(Bhi + (size_t)(n0 + lrow) * KpB + k0) + lcolB;
        const char* b1 = (const char*)(Blo + (size_t)(n0 + lrow) * KpB + k0) + lcolB;
        uint32_t so = lrow*80 + lcolB;
        cpa(dst + so,                  a0);
        cpa(dst + so + 64*80,          a0 + (size_t)64*KpA*2);
        cpa(dst + 10240 + so,          a1);
        cpa(dst + 10240 + so + 64*80,  a1 + (size_t)64*KpA*2);
        cpa(dst + 20480 + so,          b0);
        cpa(dst + 20480 + so + 64*80,  b0 + (size_t)64*KpB*2);
        cpa(dst + 30720 + so,          b1);
        cpa(dst + 30720 + so + 64*80,  b1 + (size_t)64*KpB*2);
    };
    auto compute = [&](uint32_t bb) {
        uint32_t aA = bb + (wm + (lane & 15))*80 + (lane >> 4)*16;
        uint32_t aB = bb + 20480 + (wn + (lane & 7) + ((lane >> 4) & 1)*8)*80
                    + ((lane >> 3) & 1)*16;
#pragma unroll
        for (int s = 0; s < 2; s++) {
            uint32_t ah[4][4], al[4][4], bh[2][4], bl[2][4];
#pragma unroll
            for (int mf = 0; mf < 4; mf++) ldsm4(ah[mf], aA + mf*1280 + s*32);
#pragma unroll
            for (int g = 0; g < 2; g++)  ldsm4(bh[g], aB + g*1280 + s*32);
#pragma unroll
            for (int mf = 0; mf < 4; mf++)
#pragma unroll
                for (int nf = 0; nf < 4; nf++)
                    mma16816(acc[mf][nf], ah[mf], bh[nf>>1][(nf&1)*2], bh[nf>>1][(nf&1)*2+1]);
#pragma unroll
            for (int mf = 0; mf < 4; mf++) ldsm4(al[mf], aA + 10240 + mf*1280 + s*32);
#pragma unroll
            for (int mf = 0; mf < 4; mf++)
#pragma unroll
                for (int nf = 0; nf < 4; nf++)
                    mma16816(acc[mf][nf], al[mf], bh[nf>>1][(nf&1)*2], bh[nf>>1][(nf&1)*2+1]);
#pragma unroll
            for (int g = 0; g < 2; g++)  ldsm4(bl[g], aB + 10240 + g*1280 + s*32);
#pragma unroll
            for (int mf = 0; mf < 4; mf++)
#pragma unroll
                for (int nf = 0; nf < 4; nf++)
                    mma16816(acc[mf][nf], ah[mf], bl[nf>>1][(nf&1)*2], bl[nf>>1][(nf&1)*2+1]);
        }
    };

    issue(0); CP_COMMIT();
    for (int c = 0; c < TOT; c++) {
        if (c + 1 < TOT) { issue(c + 1); CP_COMMIT(); CP_WAIT(1); }
        else CP_WAIT(0);
        __syncthreads();
        compute(sbase + (c & 1) * 40960);
        __syncthreads();
    }

    if (Cf) {
#pragma unroll
        for (int mf = 0; mf < 4; mf++) {
            int m = m0 + wm + mf*16 + (lane >> 2);
#pragma unroll
            for (int nf = 0; nf < 4; nf++) {
                int n = n0 + wn + nf*8 + (lane & 3)*2;
                if (n >= Nv) continue;
#pragma unroll
                for (int rr = 0; rr < 2; rr++) {
                    size_t off = (size_t)(m + rr*8) * Nv + n;
                    Cf[off] = acc[mf][nf][rr*2];
                    if (n + 1 < Nv) Cf[off + 1] = acc[mf][nf][rr*2 + 1];
                }
            }
        }
    } else {
#pragma unroll
        for (int mf = 0; mf < 4; mf++) {
            int m = m0 + wm + mf*16 + (lane >> 2);
#pragma unroll
            for (int nf = 0; nf < 4; nf++) {
                int n = n0 + wn + nf*8 + (lane & 3)*2;
#pragma unroll
                for (int rr = 0; rr < 2; rr++) {
                    float v0 = acc[mf][nf][rr*2], v1 = acc[mf][nf][rr*2+1];
                    size_t off = (size_t)(m + rr*8) * 512 + n;
                    __nv_bfloat162 ph, pl;
                    ph.x = __float2bfloat16(v0);
                    pl.x = __float2bfloat16(v0 - __bfloat162float(ph.x));
                    ph.y = __float2bfloat16(v1);
                    pl.y = __float2bfloat16(v1 - __bfloat162float(ph.y));
                    *(__nv_bfloat162*)&Ch[off] = ph;
                    *(__nv_bfloat162*)&Cl[off] = pl;
                }
            }
        }
    }
}

// ---------------- HMMA conv (R8 narrow, transposed gather) ----------------
template<int CS>
__global__ void __launch_bounds__(256, 2) hconv(
    const __nv_bfloat16* __restrict__ Ah, const __nv_bfloat16* __restrict__ Al,
    const __nv_bfloat16* __restrict__ Sh, const __nv_bfloat16* __restrict__ Sl,
    int Kp, int TW, int SW,
    __nv_bfloat16* __restrict__ OhT, __nv_bfloat16* __restrict__ OlT,
    int TWo, int SWo,
    float* __restrict__ Of, int ldf)
{
    extern __shared__ __align__(16) char SMC[];
    int tid = threadIdx.x, lane = tid & 31, warp = tid >> 5;
    int m0 = blockIdx.y * 128, n0 = blockIdx.x * 128;
    int wm = (warp >> 2) * 64, wn = (warp & 3) * 32;
    uint32_t sbase = smem_u32(SMC);

    float acc[4][4][4];
#pragma unroll
    for (int i = 0; i < 4; i++)
#pragma unroll
        for (int j = 0; j < 4; j++)
#pragma unroll
            for (int q = 0; q < 4; q++) acc[i][j][q] = 0.f;

    int lrow = tid >> 2, lcolB = (tid & 3) * 16;
    int bn = tid & 127, bkB = (tid >> 7) * 32;
    int gn = n0 + bn;
    int bidx = gn / TW;
    int scol = bidx * SW + (gn - bidx*TW);
    const int CPJ = CS / 32;

    auto issue = [&](int c) {
        int k0 = c << 5;
        uint32_t dst = sbase + (c & 1) * 40960;
        const char* a0 = (const char*)(Ah + (size_t)(m0 + lrow) * Kp + k0) + lcolB;
        const char* a1 = (const char*)(Al + (size_t)(m0 + lrow) * Kp + k0) + lcolB;
        uint32_t so = lrow*80 + lcolB;
        cpa(dst + so,                 a0);
        cpa(dst + so + 64*80,         a0 + (size_t)64*Kp*2);
        cpa(dst + 10240 + so,         a1);
        cpa(dst + 10240 + so + 64*80, a1 + (size_t)64*Kp*2);
        int j = c / CPJ;
        int ccB = (c - j*CPJ) * 64;
        const char* bsh = (const char*)(Sh + (size_t)(scol + j) * CS) + ccB + bkB;
        const char* bsl = (const char*)(Sl + (size_t)(scol + j) * CS) + ccB + bkB;
        uint32_t bo = bn*80 + bkB;
        cpa(dst + 20480 + bo,      bsh);
        cpa(dst + 20480 + bo + 16, bsh + 16);
        cpa(dst + 30720 + bo,      bsl);
        cpa(dst + 30720 + bo + 16, bsl + 16);
    };
    auto compute = [&](uint32_t bb) {
        uint32_t aA = bb + (wm + (lane & 15))*80 + (lane >> 4)*16;
        uint32_t aB = bb + 20480 + (wn + (lane & 7) + ((lane >> 4) & 1)*8)*80
                    + ((lane >> 3) & 1)*16;
#pragma unroll
        for (int s = 0; s < 2; s++) {
            uint32_t ah[4][4], al[4][4], bh[2][4], bl[2][4];
#pragma unroll
            for (int mf = 0; mf < 4; mf++) ldsm4(ah[mf], aA + mf*1280 + s*32);
#pragma unroll
            for (int g = 0; g < 2; g++)  ldsm4(bh[g], aB + g*1280 + s*32);
#pragma unroll
            for (int mf = 0; mf < 4; mf++)
#pragma unroll
                for (int nf = 0; nf < 4; nf++)
                    mma16816(acc[mf][nf], ah[mf], bh[nf>>1][(nf&1)*2], bh[nf>>1][(nf&1)*2+1]);
#pragma unroll
            for (int mf = 0; mf < 4; mf++) ldsm4(al[mf], aA + 10240 + mf*1280 + s*32);
#pragma unroll
            for (int mf = 0; mf < 4; mf++)
#pragma unroll
                for (int nf = 0; nf < 4; nf++)
                    mma16816(acc[mf][nf], al[mf], bh[nf>>1][(nf&1)*2], bh[nf>>1][(nf&1)*2+1]);
#pragma unroll
            for (int g = 0; g < 2; g++)  ldsm4(bl[g], aB + 10240 + g*1280 + s*32);
#pragma unroll
            for (int mf = 0; mf < 4; mf++)
#pragma unroll
                for (int nf = 0; nf < 4; nf++)
                    mma16816(acc[mf][nf], ah[mf], bl[nf>>1][(nf&1)*2], bl[nf>>1][(nf&1)*2+1]);
        }
    };

    int TOT = Kp >> 5;
    issue(0); CP_COMMIT();
    for (int c = 0; c < TOT; c++) {
        if (c + 1 < TOT) { issue(c + 1); CP_COMMIT(); CP_WAIT(1); }
        else CP_WAIT(0);
        __syncthreads();
        compute(sbase + (c & 1) * 40960);
        __syncthreads();
    }

    if (Of) {
#pragma unroll
        for (int mf = 0; mf < 4; mf++) {
            int m = m0 + wm + mf*16 + (lane >> 2);
#pragma unroll
            for (int nf = 0; nf < 4; nf++) {
                int n = n0 + wn + nf*8 + (lane & 3)*2;
                *(float2*)&Of[(size_t)m * ldf + n] =
                    make_float2(fmaxf(acc[mf][nf][0], 0.f), fmaxf(acc[mf][nf][1], 0.f));
                *(float2*)&Of[(size_t)(m + 8) * ldf + n] =
                    make_float2(fmaxf(acc[mf][nf][2], 0.f), fmaxf(acc[mf][nf][3], 0.f));
            }
        }
    } else {
        __nv_bfloat16* stage = (__nv_bfloat16*)SMC;
#pragma unroll
        for (int part = 0; part < 2; part++) {
            __syncthreads();
#pragma unroll
            for (int mf = 0; mf < 4; mf++)
#pragma unroll
                for (int nf = 0; nf < 4; nf++)
#pragma unroll
                    for (int q = 0; q < 4; q++) {
                        float v = fmaxf(acc[mf][nf][q], 0.f);
                        __nv_bfloat16 h = __float2bfloat16(v);
                        __nv_bfloat16 val = part ?
                            __float2bfloat16(v - __bfloat162float(h)) : h;
                        int nl = wn + nf*8 + (lane & 3)*2 + (q & 1);
                        int ml = wm + mf*16 + (lane >> 2) + ((q >= 2) ? 8 : 0);
                        stage[nl*136 + ml] = val;
                    }
            __syncthreads();
            __nv_bfloat16* D = part ? OlT : OhT;
            for (int u = tid; u < 2048; u += 256) {
                int r = u >> 4, seg = (u & 15) * 8;
                int gn2 = n0 + r;
                int b2 = gn2 / TWo;
                int grow = b2*SWo + (gn2 - b2*TWo);
                *(uint4*)(D + (size_t)grow*512 + m0 + seg) = *(const uint4*)(stage + r*136 + seg);
            }
        }
    }
}

// ---------------- HMMA attmix (R8) ----------------
__global__ void __launch_bounds__(192, 2) hattmix(
    const __nv_bfloat16* __restrict__ Ah, const __nv_bfloat16* __restrict__ Al,
    const __nv_bfloat16* __restrict__ Bh, const __nv_bfloat16* __restrict__ Bl,
    float* __restrict__ Y, const float* __restrict__ bias,
    const float* __restrict__ gamma, const float* __restrict__ beta,
    const float* __restrict__ resid, int do_tanh,
    __nv_bfloat16* __restrict__ ohi, __nv_bfloat16* __restrict__ olo)
{
    extern __shared__ __align__(16) char SMC[];
    int tid = threadIdx.x, lane = tid & 31, warp = tid >> 5;
    int b = blockIdx.y, g0 = blockIdx.x * 128;
    int wm = (warp >> 1) * 48, wn = (warp & 1) * 64;
    uint32_t sbase = smem_u32(SMC);

    float acc[3][8][4];
#pragma unroll
    for (int i = 0; i < 3; i++)
#pragma unroll
        for (int j = 0; j < 8; j++)
#pragma unroll
            for (int q = 0; q < 4; q++) acc[i][j][q] = 0.f;

    auto issue = [&](int c) {
        int k0 = c << 5;
        uint32_t dst = sbase + (c & 1) * 40960;
#pragma unroll
        for (int i = 0; i < 6; i++) {
            int u = tid + i * 192;
            int s = u >= 576;
            int v = u - s * 576;
            int r = v >> 2, q = v & 3;
            const char* src = (const char*)(s ? Al : Ah) + ((size_t)r*160 + k0)*2 + q*16;
            cpa(dst + s*11520 + r*80 + q*16, src);
        }
        for (int u = tid; u < 1024; u += 192) {
            int s = u >= 512;
            int v = u - s * 512;
            int r = v >> 4, q = v & 15;
            const __nv_bfloat16* src = (s ? Bl : Bh)
                + (size_t)(b*135 + k0 + r) * 512 + g0 + q*8;
            cpa(dst + 23040 + s*8704 + r*272 + q*16, src);
        }
    };
    auto compute = [&](uint32_t bb) {
        uint32_t aA = bb + (wm + (lane & 15))*80 + (lane >> 4)*16;
        uint32_t aB = bb + 23040 + (lane & 15)*272 + (wn + (lane >> 4)*8)*2;
#pragma unroll
        for (int s = 0; s < 2; s++) {
            uint32_t ah[3][4], al[3][4], bh[4][4], bl[4][4];
#pragma unroll
            for (int mf = 0; mf < 3; mf++) ldsm4(ah[mf], aA + mf*(16*80) + s*32);
#pragma unroll
            for (int nb = 0; nb < 4; nb++) ldsm4t(bh[nb], aB + s*(16*272) + nb*32);
#pragma unroll
            for (int mf = 0; mf < 3; mf++)
#pragma unroll
                for (int nf = 0; nf < 8; nf++)
                    mma16816(acc[mf][nf], ah[mf], bh[nf>>1][(nf&1)*2], bh[nf>>1][(nf&1)*2+1]);
#pragma unroll
            for (int mf = 0; mf < 3; mf++) ldsm4(al[mf], aA + 11520 + mf*(16*80) + s*32);
#pragma unroll
            for (int mf = 0; mf < 3; mf++)
#pragma unroll
                for (int nf = 0; nf < 8; nf++)
                    mma16816(acc[mf][nf], al[mf], bh[nf>>1][(nf&1)*2], bh[nf>>1][(nf&1)*2+1]);
#pragma unroll
            for (int nb = 0; nb < 4; nb++) ldsm4t(bl[nb], aB + 8704 + s*(16*272) + nb*32);
#pragma unroll
            for (int mf = 0; mf < 3; mf++)
#pragma unroll
                for (int nf = 0; nf < 8; nf++)
                    mma16816(acc[mf][nf], ah[mf], bl[nf>>1][(nf&1)*2], bl[nf>>1][(nf&1)*2+1]);
        }
    };

    const int TOT = 5;
    issue(0); CP_COMMIT();
    for (int c = 0; c < TOT; c++) {
        if (c + 1 < TOT) { issue(c + 1); CP_COMMIT(); CP_WAIT(1); }
        else CP_WAIT(0);
        __syncthreads();
        compute(sbase + (c & 1) * 40960);
        __syncthreads();
    }

#pragma unroll
    for (int mf = 0; mf < 3; mf++) {
        int mb = wm + mf*16 + (lane >> 2);
#pragma unroll
        for (int rr = 0; rr < 2; rr++) {
            int m = mb + rr*8;
            if (m >= 135) continue;
            size_t row = ((size_t)b*135 + m) * 512;
#pragma unroll
            for (int nf = 0; nf < 8; nf++) {
                int n = g0 + wn + nf*8 + (lane & 3)*2;
                float v0 = acc[mf][nf][rr*2]     + bias[n];
                float v1 = acc[mf][nf][rr*2 + 1] + bias[n + 1];
                if (gamma) {
                    int gi = m*512 + n;
                    v0 = gamma[gi]*(v0*BN_SCALEF) + beta[gi];
                    v1 = gamma[gi+1]*(v1*BN_SCALEF) + beta[gi+1];
                }
                if (do_tanh) { v0 = tanhf(v0); v1 = tanhf(v1); }
                if (resid) { v0 += resid[row + n]; v1 += resid[row + n + 1]; }
                *(float2*)&Y[row + n] = make_float2(v0, v1);
                if (ohi) {
                    __nv_bfloat162 ph, pl;
                    ph.x = __float2bfloat16(v0);
                    pl.x = __float2bfloat16(v0 - __bfloat162float(ph.x));
                    ph.y = __float2bfloat16(v1);
                    pl.y = __float2bfloat16(v1 - __bfloat162float(ph.y));
                    *(__nv_bfloat162*)&ohi[row + n] = ph;
                    *(__nv_bfloat162*)&olo[row + n] = pl;
                }
            }
        }
    }
}

// ---------------- conv GEMM (scalar, query branch) ----------------
template<int CS, int CSV>
__global__ void __launch_bounds__(256, 2) conv_gemm(
    const float* __restrict__ A, const float* __restrict__ src, float* __restrict__ C,
    int M, int N, int K, int LD, int TW, int SW, int WOFF,
    int ldc, int TWo, int SWo, int relu, int kchunk)
{
    __shared__ __align__(16) float As[2][16][132];
    __shared__ __align__(16) float Bs[2][16][128];
    int tid = threadIdx.x;
    int m0 = blockIdx.y * 128, n0 = blockIdx.x * 128;
    int tx4 = (tid & 15) * 4, ty4 = (tid >> 4) * 4;
    int arow = tid >> 1, akq = (tid & 1) * 8;
    int kbeg = blockIdx.z * kchunk;
    int kend = min(K, kbeg + kchunk);

    int nloc = tid & 127;
    int krow0 = (tid >> 7) * 8;
    int gn_b = n0 + nloc;
    int bidx = gn_b / TW;
    size_t bcolb = (size_t)bidx * SW + (gn_b - bidx*TW) + WOFF;

    ull acc[8][4];
#pragma unroll
    for (int i = 0; i < 8; i++)
#pragma unroll
        for (int j = 0; j < 4; j++) acc[i][j] = 0ULL;

    const float* Ap = A + (size_t)(m0 + arow) * K;
    const float4 z4 = make_float4(0.f,0.f,0.f,0.f);
    float4 ra0, ra1; float rb[8];

    auto loadT = [&](int k0) {
        int gk = k0 + akq;
        ra0 = (gk     < kend) ? *(const float4*)(Ap + gk)     : z4;
        ra1 = (gk + 4 < kend) ? *(const float4*)(Ap + gk + 4) : z4;
#pragma unroll
        for (int i = 0; i < 8; i++) {
            int gkk = k0 + krow0 + i;
            float v = 0.f;
            if (gkk < kend && gn_b < N) {
                int j = gkk / CS; int c = gkk - j*CS;
                if (c < CSV) v = src[(size_t)c*LD + bcolb + j];
            }
            rb[i] = v;
        }
    };
    auto storeT = [&](int buf) {
        As[buf][akq+0][arow] = ra0.x; As[buf][akq+1][arow] = ra0.y;
        As[buf][akq+2][arow] = ra0.z; As[buf][akq+3][arow] = ra0.w;
        As[buf][akq+4][arow] = ra1.x; As[buf][akq+5][arow] = ra1.y;
        As[buf][akq+6][arow] = ra1.z; As[buf][akq+7][arow] = ra1.w;
#pragma unroll
        for (int i = 0; i < 8; i++) Bs[buf][krow0+i][nloc] = rb[i];
    };
    auto compute = [&](int buf) {
#pragma unroll
        for (int kk = 0; kk < 16; kk++) {
            float4 aL = *(const float4*)&As[buf][kk][ty4];
            float4 aH = *(const float4*)&As[buf][kk][ty4 + 64];
            longlong2 bL = *(const longlong2*)&Bs[buf][kk][tx4];
            longlong2 bH = *(const longlong2*)&Bs[buf][kk][tx4 + 64];
            ull bb0 = (ull)bL.x, bb1 = (ull)bL.y, bb2 = (ull)bH.x, bb3 = (ull)bH.y;
            float av[8] = {aL.x,aL.y,aL.z,aL.w,aH.x,aH.y,aH.z,aH.w};
#pragma unroll
            for (int i = 0; i < 8; i++) {
                ull aa = packf2(av[i]);
                ffma2(acc[i][0], aa, bb0);
                ffma2(acc[i][1], aa, bb1);
                ffma2(acc[i][2], aa, bb2);
                ffma2(acc[i][3], aa, bb3);
            }
        }
    };

    int nk = (kend - kbeg + 15) >> 4;
    loadT(kbeg); storeT(0); __syncthreads();
    for (int kt = 0; kt < nk; kt++) {
        int buf = kt & 1;
        if (kt + 1 < nk) loadT(kbeg + ((kt + 1) << 4));
        compute(buf);
        if (kt + 1 < nk) storeT(buf ^ 1);
        __syncthreads();
    }

    C += (size_t)blockIdx.z * M * N;
#pragma unroll
    for (int i = 0; i < 8; i++) {
        int gm = m0 + ty4 + (i < 4 ? i : 60 + i);
        float* Cp = C + (size_t)gm * ldc;
#pragma unroll
        for (int j = 0; j < 4; j++) {
            float2 v = unpk(acc[i][j]);
            int gn = n0 + tx4 + (j < 2 ? 2*j : 60 + 2*j);
            float vx = relu ? fmaxf(v.x, 0.f) : v.x;
            float vy = relu ? fmaxf(v.y, 0.f) : v.y;
            if (gn < N) {
                int col = TWo ? (gn/TWo)*SWo + gn%TWo : gn;
                Cp[col] = vx;
            }
            if (gn + 1 < N) {
                int g1 = gn + 1;
                int col = TWo ? (g1/TWo)*SWo + g1%TWo : g1;
                Cp[col] = vy;
            }
        }
    }
}

__global__ void reduce_remap(const float* __restrict__ part, float* __restrict__ C,
                             int M, int N, int S, int ldo, int TWo, int SWo) {
    int i = blockIdx.x * 256 + threadIdx.x;
    if (i >= M * N) return;
    int m = i / N, n = i - m*N;
    float a = 0.f;
    for (int s = 0; s < S; s++) a += part[(size_t)s*M*N + i];
    int col = TWo ? (n/TWo)*SWo + n%TWo : n;
    C[(size_t)m*ldo + col] = fmaxf(a, 0.f);
}

// ---------------- attention scores + normalization ----------------
__global__ void att_kernel() {
    int b = blockIdx.x, t = threadIdx.x;
    float s = 0.f;
    if (t < VN) {
        for (int o = 0; o < 512; o++)
            s += g_qryf[o*N2Q + b] * g_keyf[(size_t)o*N2K + b*VN + t];
        s += 1e-15f;
    }
    __shared__ float sm[128];
    sm[t] = (t < VN) ? s : 0.f;
    __syncthreads();
    for (int off = 64; off > 0; off >>= 1) {
        if (t < off) sm[t] += sm[t + off];
        __syncthreads();
    }
    if (t < VN) g_att[b*VN + t] = s / sm[0];
}

// ---------------- build x (+ bf16 splits padded to 96) ----------------
__global__ void build_x(const float* __restrict__ poses) {
    int b = blockIdx.x, tid = threadIdx.x;
    __shared__ float s_att[VN];
    __shared__ float s_ws[VL*INF];
    __shared__ float s_dct[VL*VL];
    if (tid < VN) s_att[tid] = g_att[b*VN + tid];
    for (int i = tid; i < VL*VL; i += 256) s_dct[i] = g_dct[i];
    __syncthreads();
    const float* pb = poses + (size_t)b * 144 * INF;
    for (int i = tid; i < VL*INF; i += 256) {
        int t = i / INF, f = i - t*INF;
        float acc = 0.f;
        for (int v = 0; v < VN; v++) acc += s_att[v] * pb[(v + t)*INF + f];
        s_ws[i] = acc;
    }
    __syncthreads();
    float* xb = g_x + (size_t)b * INF * 68;
    size_t xrow = (size_t)b * INF * 96;
    for (int i = tid; i < INF*VL; i += 256) {
        int f = i / VL, k = i - f*VL;
        float a0 = 0.f, a1 = 0.f;
        for (int t = 0; t < VL; t++) {
            float d = s_dct[k*VL + t];
            int pt = (t < KQ) ? (110 + t) : 119;
            a0 += d * pb[pt*INF + f];
            a1 += d * s_ws[t*INF + f];
        }
        xb[f*68 + k]      = a0;
        xb[f*68 + 34 + k] = a1;
        __nv_bfloat16 h0 = __float2bfloat16(a0);
        g_xh[xrow + f*96 + k] = h0;
        g_xl[xrow + f*96 + k] = __float2bfloat16(a0 - __bfloat162float(h0));
        __nv_bfloat16 h1 = __float2bfloat16(a1);
        g_xh[xrow + f*96 + 34 + k] = h1;
        g_xl[xrow + f*96 + 34 + k] = __float2bfloat16(a1 - __bfloat162float(h1));
    }
    // zero pad cols 68..95
    for (int i = tid; i < INF*28; i += 256) {
        int f = i / 28, k = 68 + i - f*28;
        g_xh[xrow + f*96 + k] = __float2bfloat16(0.f);
        g_xl[xrow + f*96 + k] = __float2bfloat16(0.f);
    }
}

// ---------------- scalar att-mix (gc7 only; t1 ld=68) ----------------
__global__ void __launch_bounds__(256, 2) attmix(
    const float* __restrict__ AT, const float* __restrict__ Bm, float* __restrict__ Cm,
    int N, const float* __restrict__ bias,
    const float* __restrict__ resid)
{
    __shared__ __align__(16) float Asm[27][148];
    int tid = threadIdx.x;
    int b = blockIdx.y;
    int n0 = blockIdx.x * 128;
    int colg = tid & 63;
    int grp  = tid >> 6;
    int nbase = grp * 36;
    int col0 = n0 + colg, col1 = col0 + 64;
    bool c0 = col0 < N, c1 = col1 < N;
    ull accA[18], accB[18];
#pragma unroll
    for (int i = 0; i < 18; i++) { accA[i] = 0ULL; accB[i] = 0ULL; }
    const float* Bb = Bm + (size_t)b * 135 * N;

    for (int mc = 0; mc < 135; mc += 27) {
        __syncthreads();
        for (int i = tid; i < 27*144; i += 256) {
            int mm = i / 144, n = i - mm*144;
            Asm[mm][n] = AT[(mc + mm)*144 + n];
        }
        __syncthreads();
        for (int mm = 0; mm < 27; mm++) {
            size_t off = (size_t)(mc + mm) * N;
            float b0 = c0 ? Bb[off + col0] : 0.f;
            float b1 = c1 ? Bb[off + col1] : 0.f;
            ull bb0 = packf2(b0), bb1 = packf2(b1);
            const longlong2* ap = (const longlong2*)&Asm[mm][nbase];
#pragma unroll
            for (int i = 0; i < 9; i++) {
                longlong2 av = ap[i];
                ffma2(accA[2*i],   (ull)av.x, bb0);
                ffma2(accB[2*i],   (ull)av.x, bb1);
                ffma2(accA[2*i+1], (ull)av.y, bb0);
                ffma2(accB[2*i+1], (ull)av.y, bb1);
            }
        }
    }

    float bias0 = c0 ? bias[col0] : 0.f;
    float bias1 = c1 ? bias[col1] : 0.f;
    size_t crow = (size_t)b * 135 * N;
#pragma unroll
    for (int i = 0; i < 18; i++) {
        float2 vA = unpk(accA[i]);
        float2 vB = unpk(accB[i]);
#pragma unroll
        for (int r = 0; r < 2; r++) {
            int n = nbase + 2*i + r;
            if (n >= 135) continue;
            float va = (r == 0) ? vA.x : vA.y;
            float vb = (r == 0) ? vB.x : vB.y;
            size_t rowoff = crow + (size_t)n * N;
            if (c0) Cm[rowoff + col0] = va + bias0 + (resid ? resid[rowoff + col0] : 0.f);
            if (c1) Cm[rowoff + col1] = vb + bias1 + (resid ? resid[rowoff + col1] : 0.f);
        }
    }
}

// ---------------- final IDCT ----------------
__global__ void final_idct(float* __restrict__ out) {
    int i = blockIdx.x * 256 + threadIdx.x;
    if (i >= NB*OUTN*INF) return;
    int f = i % INF; int r = i / INF;
    int ti = r % OUTN; int b = r / OUTN;
    const float* yb = g_t2 + (size_t)b*INF*68 + (size_t)f*68;
    int t = KQ + ti;
    float acc = 0.f;
    for (int k = 0; k < DCTN; k++) acc += g_dct[k*VL + t] * yb[k];
    out[i] = acc;
}

// ---------------- launch ----------------
extern "C" void kernel_launch(void* const* d_in, const int* in_sizes, int n_in,
                              void* d_out, int out_size)
{
    (void)in_sizes; (void)n_in; (void)out_size;
    const float* poses   = (const float*)d_in[0];
    const float* qw1     = (const float*)d_in[1];
    const float* qw2     = (const float*)d_in[2];
    const float* kw1     = (const float*)d_in[3];
    const float* kw2     = (const float*)d_in[4];
    const float* gc1_att = (const float*)d_in[5];
    const float* gc1_w   = (const float*)d_in[6];
    const float* gc1_b   = (const float*)d_in[7];
    const float* bn1_g   = (const float*)d_in[8];
    const float* bn1_b   = (const float*)d_in[9];
    const float* gcb_att = (const float*)d_in[10];
    const float* gcb_w   = (const float*)d_in[11];
    const float* gcb_b   = (const float*)d_in[12];
    const float* gcb_g   = (const float*)d_in[13];
    const float* gcb_beta= (const float*)d_in[14];
    const float* gc7_att = (const float*)d_in[15];
    const float* gc7_w   = (const float*)d_in[16];
    const float* gc7_b   = (const float*)d_in[17];
    float* out = (float*)d_out;

    void *pv;
    cudaGetSymbolAddress(&pv, g_postf); float* postf = (float*)pv;
    cudaGetSymbolAddress(&pv, g_pfTh);  __nv_bfloat16* pfTh = (__nv_bfloat16*)pv;
    cudaGetSymbolAddress(&pv, g_pfTl);  __nv_bfloat16* pfTl = (__nv_bfloat16*)pv;
    cudaGetSymbolAddress(&pv, g_w1h);   __nv_bfloat16* w1h = (__nv_bfloat16*)pv;
    cudaGetSymbolAddress(&pv, g_w1l);   __nv_bfloat16* w1l = (__nv_bfloat16*)pv;
    cudaGetSymbolAddress(&pv, g_w2h);   __nv_bfloat16* w2h = (__nv_bfloat16*)pv;
    cudaGetSymbolAddress(&pv, g_w2l);   __nv_bfloat16* w2l = (__nv_bfloat16*)pv;
    cudaGetSymbolAddress(&pv, g_h1kTh); __nv_bfloat16* h1kTh = (__nv_bfloat16*)pv;
    cudaGetSymbolAddress(&pv, g_h1kTl); __nv_bfloat16* h1kTl = (__nv_bfloat16*)pv;
    cudaGetSymbolAddress(&pv, g_q1p);   float* q1p   = (float*)pv;
    cudaGetSymbolAddress(&pv, g_q2p);   float* q2p   = (float*)pv;
    cudaGetSymbolAddress(&pv, g_h1q);   float* h1q   = (float*)pv;
    cudaGetSymbolAddress(&pv, g_keyf);  float* keyf  = (float*)pv;
    cudaGetSymbolAddress(&pv, g_qryf);  float* qryf  = (float*)pv;
    cudaGetSymbolAddress(&pv, g_part);  float* part  = (float*)pv;
    cudaGetSymbolAddress(&pv, g_attT);  float* attT  = (float*)pv;
    cudaGetSymbolAddress(&pv, g_atth);  __nv_bfloat16* atth = (__nv_bfloat16*)pv;
    cudaGetSymbolAddress(&pv, g_attl);  __nv_bfloat16* attl = (__nv_bfloat16*)pv;
    cudaGetSymbolAddress(&pv, g_x);     float* xp    = (float*)pv;
    cudaGetSymbolAddress(&pv, g_xh);    __nv_bfloat16* xh = (__nv_bfloat16*)pv;
    cudaGetSymbolAddress(&pv, g_xl);    __nv_bfloat16* xl = (__nv_bfloat16*)pv;
    cudaGetSymbolAddress(&pv, g_wt1h);  __nv_bfloat16* wt1h = (__nv_bfloat16*)pv;
    cudaGetSymbolAddress(&pv, g_wt1l);  __nv_bfloat16* wt1l = (__nv_bfloat16*)pv;
    cudaGetSymbolAddress(&pv, g_wt7h);  __nv_bfloat16* wt7h = (__nv_bfloat16*)pv;
    cudaGetSymbolAddress(&pv, g_wt7l);  __nv_bfloat16* wt7l = (__nv_bfloat16*)pv;
    cudaGetSymbolAddress(&pv, g_t1);    float* t1p   = (float*)pv;
    cudaGetSymbolAddress(&pv, g_t1h);   __nv_bfloat16* t1h = (__nv_bfloat16*)pv;
    cudaGetSymbolAddress(&pv, g_t1l);   __nv_bfloat16* t1l = (__nv_bfloat16*)pv;
    cudaGetSymbolAddress(&pv, g_t2);    float* t2p   = (float*)pv;
    cudaGetSymbolAddress(&pv, g_y);     float* yp    = (float*)pv;
    cudaGetSymbolAddress(&pv, g_s0h);   __nv_bfloat16* s0h = (__nv_bfloat16*)pv;
    cudaGetSymbolAddress(&pv, g_s0l);   __nv_bfloat16* s0l = (__nv_bfloat16*)pv;
    cudaGetSymbolAddress(&pv, g_s1h);   __nv_bfloat16* s1h = (__nv_bfloat16*)pv;
    cudaGetSymbolAddress(&pv, g_s1l);   __nv_bfloat16* s1l = (__nv_bfloat16*)pv;
    cudaGetSymbolAddress(&pv, g_wth);   __nv_bfloat16* wth = (__nv_bfloat16*)pv;
    cudaGetSymbolAddress(&pv, g_wtl);   __nv_bfloat16* wtl = (__nv_bfloat16*)pv;

    cudaFuncSetAttribute(hgemm_gen, cudaFuncAttributeMaxDynamicSharedMemorySize, HG_SMEM);
    cudaFuncSetAttribute(hconv<160>, cudaFuncAttributeMaxDynamicSharedMemorySize, HG_SMEM);
    cudaFuncSetAttribute(hconv<512>, cudaFuncAttributeMaxDynamicSharedMemorySize, HG_SMEM);
    cudaFuncSetAttribute(hattmix, cudaFuncAttributeMaxDynamicSharedMemorySize, HG_SMEM);

    // --- launch #4 = hconv<512> (the ncu-profiled slot) ---
    pack_ws_all<<<(512*3520 + 255)/256, 256>>>(kw1, kw2);                 // 1
    pose_pfT<<<(NPOS1*160 + 255)/256, 256>>>(poses);                      // 2
    hconv<160><<<dim3(182, 4), 256, HG_SMEM>>>(w1h, w1l, pfTh, pfTl,      // 3
        960, 91, 120, h1kTh, h1kTl, 91, 96, (float*)0, 0);
    hconv<512><<<dim3(174, 4), 256, HG_SMEM>>>(w2h, w2l, h1kTh, h1kTl,    // 4 <- profiled
        2560, 87, 96, (__nv_bfloat16*)0, (__nv_bfloat16*)0, 0, 0, keyf, N2K);

    init_dct<<<5, 256>>>();
    transpose_postf<<<(INF*LDPF + 255)/256, 256>>>(poses);

    // query branch (scalar, small)
    pack_w<<<(512*816 + 255)/256, 256>>>(qw1, q1p, 512, 135, 6, 136);
    conv_gemm<136,135><<<dim3(N1Q/128, 4, 3), 256>>>(q1p, postf, part,
        512, N1Q, 816, LDPF, 5, 120, 110, N1Q, 0, 0, 0, 272);
    reduce_remap<<<(512*N1Q + 255)/256, 256>>>(part, h1q, 512, N1Q, 3, LDQ1, 5, 12);
    pack_w<<<(512*2560 + 255)/256, 256>>>(qw2, q2p, 512, 512, 5, 512);
    conv_gemm<512,512><<<dim3(N2Q/128, 4, 10), 256>>>(q2p, h1q, part,
        512, N2Q, 2560, LDQ1, 1, 12, 0, N2Q, 0, 0, 0, 256);
    reduce_remap<<<(512*N2Q + 255)/256, 256>>>(part, qryf, 512, N2Q, 10, N2Q, 0, 0);

    pack_att<<<(6*135*144 + 255)/256, 256>>>(gc1_att, gcb_att, gc7_att);
    pack_atts<<<(5*144*160 + 255)/256, 256>>>(gc1_att, gcb_att);
    pack_wt_split<<<(4*512*512 + 255)/256, 256>>>(gcb_w);
    pack_wt17<<<(512*96 + 128*512 + 255)/256, 256>>>(gc1_w, gc7_w);
    att_kernel<<<NB, 128>>>();
    build_x<<<NB, 256>>>(poses);

    // gc1: HMMA GEMM (x splits @ wt1) -> t1 splits; HMMA attmix -> yp + s0
    hgemm_gen<<<dim3(4, 270), 256, HG_SMEM>>>(xh, xl, 96, wt1h, wt1l, 96, 3,
                                              t1h, t1l, (float*)0, 0);
    hattmix<<<dim3(4, NB), 192, HG_SMEM>>>(atth, attl, t1h, t1l, yp,
        gc1_b, bn1_g, bn1_b, (const float*)0, 1, s0h, s0l);

    // 4 gcb layers: HMMA GEMM + HMMA attmix (l==3 emits yp splits to s0)
    for (int l = 0; l < 4; l++) {
        const __nv_bfloat16* ah = (l & 1) ? s1h : s0h;
        const __nv_bfloat16* al = (l & 1) ? s1l : s0l;
        __nv_bfloat16* oh = (l & 1) ? s0h : s1h;
        __nv_bfloat16* ol = (l & 1) ? s0l : s1l;
        float*       o   = (l & 1) ? yp  : t2p;
        const float* res = (l & 1) ? yp  : (const float*)0;
        hgemm_gen<<<dim3(4, 270), 256, HG_SMEM>>>(ah, al, 512,
            wth + (size_t)l*262144, wtl + (size_t)l*262144, 512, 16,
            t1h, t1l, (float*)0, 0);
        hattmix<<<dim3(4, NB), 192, HG_SMEM>>>(
            atth + (size_t)(1+l)*144*160, attl + (size_t)(1+l)*144*160,
            t1h, t1l, o,
            gcb_b + (size_t)l*512,
            gcb_g + (size_t)l*69120, gcb_beta + (size_t)l*69120,
            res, 1, oh, ol);
    }

    // gc7: HMMA GEMM (yp splits in s0 @ wt7) -> fp32 t1 (ld 68); scalar attmix
    hgemm_gen<<<dim3(1, 270), 256, HG_SMEM>>>(s0h, s0l, 512, wt7h, wt7l, 512, 16,
                                              (__nv_bfloat16*)0, (__nv_bfloat16*)0,
                                              t1p, 68);
    attmix<<<dim3(1, NB), 256>>>(attT + (size_t)5*135*144, t1p, t2p, 68, gc7_b, xp);

    final_idct<<<(NB*OUTN*INF + 255)/256, 256>>>(out);
}